// round 13
// baseline (speedup 1.0000x reference)
#include <cuda_runtime.h>
#include <cuda_fp16.h>
#include <math.h>
#include <stdint.h>

#define BATCH 2
#define SEQ   2048
#define CLEN  2048
#define NH    16
#define NKVH  4
#define HD    128
#define HIDDIM 2048
#define EPSF  1e-6f
#define QSCL  (0.08838834764831845f * 1.4426950408889634f)

// ---------------- scratch (device globals) ---------------------------------
__device__ __half g_x16[BATCH*SEQ*HIDDIM];
__device__ __half g_c16[BATCH*SEQ*HIDDIM];
__device__ __half g_q16[BATCH*SEQ*HIDDIM];
__device__ __half g_k16[BATCH*NKVH*CLEN*HD];
__device__ __half g_v16[BATCH*NKVH*CLEN*HD];
__device__ __half g_wqT [HIDDIM*HIDDIM];
__device__ __half g_wkvT[HIDDIM*NKVH*HD*2];
__device__ __half g_woT [HIDDIM*HIDDIM];

// ======================= helpers ============================================
__device__ __forceinline__ uint32_t smem_u32(const void* p) {
    uint32_t a;
    asm("{ .reg .u64 t; cvta.to.shared.u64 t, %1; cvt.u32.u64 %0, t; }" : "=r"(a) : "l"(p));
    return a;
}
__device__ __forceinline__ void cpa16(uint32_t d, const void* g) {
    asm volatile("cp.async.cg.shared.global [%0], [%1], 16;" :: "r"(d), "l"(g) : "memory");
}
#define CP_COMMIT() asm volatile("cp.async.commit_group;" ::: "memory")

__device__ __forceinline__ void ldsm4(uint32_t& r0, uint32_t& r1, uint32_t& r2, uint32_t& r3,
                                      uint32_t a) {
    asm volatile("ldmatrix.sync.aligned.m8n8.x4.shared.b16 {%0,%1,%2,%3}, [%4];"
                 : "=r"(r0), "=r"(r1), "=r"(r2), "=r"(r3) : "r"(a));
}
__device__ __forceinline__ void ldsm4t(uint32_t& r0, uint32_t& r1, uint32_t& r2, uint32_t& r3,
                                       uint32_t a) {
    asm volatile("ldmatrix.sync.aligned.m8n8.x4.trans.shared.b16 {%0,%1,%2,%3}, [%4];"
                 : "=r"(r0), "=r"(r1), "=r"(r2), "=r"(r3) : "r"(a));
}
__device__ __forceinline__ void mma16816(float* c, const uint32_t* a, uint32_t b0, uint32_t b1) {
    asm volatile(
        "mma.sync.aligned.m16n8k16.row.col.f32.f16.f16.f32 "
        "{%0,%1,%2,%3}, {%4,%5,%6,%7}, {%8,%9}, {%0,%1,%2,%3};"
        : "+f"(c[0]), "+f"(c[1]), "+f"(c[2]), "+f"(c[3])
        : "r"(a[0]), "r"(a[1]), "r"(a[2]), "r"(a[3]), "r"(b0), "r"(b1));
}
__device__ __forceinline__ uint32_t packh2(float a, float b) {
    __half2 h = __floats2half2_rn(a, b);
    return *(uint32_t*)&h;
}
__device__ __forceinline__ float ex2f(float x) {
    float y;
    asm("ex2.approx.f32 %0, %1;" : "=f"(y) : "f"(x));
    return y;
}

// ---------------- fused prep kernel -----------------------------------------
#define NF4 ((size_t)BATCH * SEQ * HIDDIM / 4)

__global__ __launch_bounds__(256) void prep_kernel(
    const float4* __restrict__ x, const float4* __restrict__ c,
    const float* __restrict__ wq, const float* __restrict__ wkv,
    const float* __restrict__ wo,
    __half* __restrict__ x16, __half* __restrict__ c16,
    __half* __restrict__ wqT, __half* __restrict__ wkvT, __half* __restrict__ woT)
{
    __shared__ float s[32][33];
    int bid = blockIdx.x;

    if (bid < 16384) {
        size_t i = (size_t)bid * 256 + threadIdx.x;
        const float4* src; __half* dst; size_t j;
        if (i < NF4) { src = x; dst = x16; j = i; }
        else         { src = c; dst = c16; j = i - NF4; }
        float4 v = src[j];
        ((__half2*)dst)[j * 2]     = __floats2half2_rn(v.x, v.y);
        ((__half2*)dst)[j * 2 + 1] = __floats2half2_rn(v.z, v.w);
        return;
    }
    bid -= 16384;

    const float* w; __half* o; int N;
    if (bid < 4096)      {              w = wq;  o = wqT;  N = HIDDIM; }
    else if (bid < 6144) { bid -= 4096; w = wkv; o = wkvT; N = NKVH * HD * 2; }
    else                 { bid -= 6144; w = wo;  o = woT;  N = HIDDIM; }

    const int K = HIDDIM;
    int nb = N / 32;
    int n0 = (bid % nb) * 32, k0 = (bid / nb) * 32;
    int tx = threadIdx.x & 31, ty = threadIdx.x >> 5;
#pragma unroll
    for (int i = ty; i < 32; i += 8)
        s[i][tx] = w[(size_t)(k0 + i) * N + n0 + tx];
    __syncthreads();
#pragma unroll
    for (int j = ty; j < 32; j += 8)
        o[(size_t)(n0 + j) * K + k0 + tx] = __float2half_rn(s[tx][j]);
}

// ============ GEMM mainloop macro (128x256, occ 1, no end-barrier) =========
#define TP2  80
#define A_T  (128 * TP2)             // 10240
#define B_T  (256 * TP2)             // 20480
#define STB1 (A_T + B_T)             // 30720
#define NST1 3

#define GEMM_MAINLOOP256(APTR, BPTR, BNVAL, KDIM)                                \
    extern __shared__ char smc[];                                                \
    const uint32_t sb = smem_u32(smc);                                           \
    const int tid  = threadIdx.x;                                                \
    const int lane = tid & 31;                                                   \
    const int wid  = tid >> 5;                                                   \
    const int wm   = wid & 1;                                                    \
    const int wn   = wid >> 1;                                                   \
    const int bm   = blockIdx.y * 128;                                           \
    const int bn   = (BNVAL);                                                    \
    const int arow = tid >> 1;                                                   \
    const int ahalf = tid & 1;                                                   \
    const size_t gA = (size_t)(bm + arow) * (KDIM) + ahalf * 16;                 \
    const uint32_t sA = arow * TP2 + ahalf * 32;                                 \
    const size_t gB = (size_t)(bn + tid) * (KDIM);                               \
    const uint32_t sB = tid * TP2;                                               \
    const uint32_t laneOff = (lane & 15) * TP2 + (lane >> 4) * 16;               \
    float acc[4][8][4];                                                          \
    _Pragma("unroll")                                                            \
    for (int i = 0; i < 4; i++)                                                  \
        _Pragma("unroll")                                                        \
        for (int j = 0; j < 8; j++)                                              \
            _Pragma("unroll")                                                    \
            for (int r = 0; r < 4; r++) acc[i][j][r] = 0.f;                      \
    const int nst = (KDIM) / 32;                                                 \
    auto loadStage = [&](int s, int buf) {                                       \
        uint32_t st = sb + buf * STB1;                                           \
        int k0 = s * 32;                                                         \
        cpa16(st + sA,      (APTR) + gA + k0);                                   \
        cpa16(st + sA + 16, (APTR) + gA + k0 + 8);                               \
        uint32_t bb = st + A_T + sB;                                             \
        cpa16(bb,      (BPTR) + gB + k0);                                        \
        cpa16(bb + 16, (BPTR) + gB + k0 + 8);                                    \
        cpa16(bb + 32, (BPTR) + gB + k0 + 16);                                   \
        cpa16(bb + 48, (BPTR) + gB + k0 + 24);                                   \
        CP_COMMIT();                                                             \
    };                                                                           \
    loadStage(0, 0);                                                             \
    loadStage(1, 1);                                                             \
    int buf = 0;                                                                 \
    for (int s = 0; s < nst; ++s) {                                              \
        if (s + 1 < nst) asm volatile("cp.async.wait_group 1;" ::: "memory");    \
        else             asm volatile("cp.async.wait_group 0;" ::: "memory");    \
        __syncthreads();                                                         \
        if (s + 2 < nst) loadStage(s + 2, (buf + 2) % NST1);                     \
        uint32_t st = sb + buf * STB1;                                           \
        uint32_t aBase  = st + (wm * 64) * TP2 + laneOff;                        \
        uint32_t bBase  = st + A_T + (wn * 64) * TP2 + laneOff;                  \
        _Pragma("unroll")                                                        \
        for (int ks = 0; ks < 2; ++ks) {                                         \
            uint32_t ko = ks * 32;                                               \
            uint32_t af[4][4];                                                   \
            _Pragma("unroll")                                                    \
            for (int mi = 0; mi < 4; ++mi)                                       \
                ldsm4(af[mi][0], af[mi][1], af[mi][2], af[mi][3],                \
                      aBase + mi * 16 * TP2 + ko);                               \
            _Pragma("unroll")                                                    \
            for (int bi = 0; bi < 4; ++bi) {                                     \
                uint32_t bf[4];                                                  \
                ldsm4(bf[0], bf[1], bf[2], bf[3], bBase + bi * 16 * TP2 + ko);   \
                _Pragma("unroll")                                                \
                for (int mi = 0; mi < 4; ++mi) {                                 \
                    _Pragma("unroll")                                            \
                    for (int sub = 0; sub < 2; ++sub)                            \
                        mma16816(acc[mi][bi * 2 + sub], af[mi], bf[sub], bf[sub + 2]); \
                }                                                                \
            }                                                                    \
        }                                                                        \
        buf = (buf + 1) % NST1;                                                  \
    }

// ---------------- O-projection GEMM (128x256, occ 1, fp32 out) -------------
__global__ __launch_bounds__(256, 1) void gemm_o_kernel(
    const __half* __restrict__ A, const __half* __restrict__ Bh,
    float* __restrict__ C, int M, int N, int K)
{
    GEMM_MAINLOOP256(A, Bh, blockIdx.x * 256, K)
    const int g  = lane >> 2;
    const int q4 = lane & 3;
#pragma unroll
    for (int mi = 0; mi < 4; ++mi) {
#pragma unroll
        for (int nj = 0; nj < 8; ++nj) {
            int r0 = bm + wm * 64 + mi * 16 + g;
            int c0 = bn + wn * 64 + nj * 8 + q4 * 2;
            *(float2*)(C + (size_t)r0 * N + c0)       = make_float2(acc[mi][nj][0], acc[mi][nj][1]);
            *(float2*)(C + (size_t)(r0 + 8) * N + c0) = make_float2(acc[mi][nj][2], acc[mi][nj][3]);
        }
    }
}

// ---------------- unified Q-proj + KV-proj GEMM (128x256, occ 1) -----------
__global__ __launch_bounds__(256, 1) void gemm_qkv_fused_kernel(
    const __half* __restrict__ x16a, const __half* __restrict__ wqT,
    const float* __restrict__ nqw, __half* __restrict__ q16,
    const __half* __restrict__ c16a, const __half* __restrict__ wkvT,
    const float* __restrict__ nkw, __half* __restrict__ k16,
    __half* __restrict__ v16)
{
    const bool isQ = blockIdx.x < 8;
    const __half* Ap = isQ ? x16a : c16a;
    const __half* Bp = isQ ? wqT : wkvT;
    const int bnIdx = isQ ? blockIdx.x : blockIdx.x - 8;

    GEMM_MAINLOOP256(Ap, Bp, bnIdx * 256, HIDDIM)

    __syncthreads();   // mainloop has no trailing barrier; protect smem reuse
    float* red = (float*)smc;
    const int g  = lane >> 2;
    const int q4 = lane & 3;

    if (isQ) {
        const int N = HIDDIM;
#pragma unroll
        for (int mi = 0; mi < 4; ++mi) {
            float s0 = 0.f, s1 = 0.f;
#pragma unroll
            for (int nj = 0; nj < 8; ++nj) {
                s0 += acc[mi][nj][0] * acc[mi][nj][0] + acc[mi][nj][1] * acc[mi][nj][1];
                s1 += acc[mi][nj][2] * acc[mi][nj][2] + acc[mi][nj][3] * acc[mi][nj][3];
            }
            s0 += __shfl_xor_sync(0xffffffffu, s0, 1);
            s0 += __shfl_xor_sync(0xffffffffu, s0, 2);
            s1 += __shfl_xor_sync(0xffffffffu, s1, 1);
            s1 += __shfl_xor_sync(0xffffffffu, s1, 2);
            if (q4 == 0) {
                red[wid * 64 + mi * 16 + g]     = s0;
                red[wid * 64 + mi * 16 + g + 8] = s1;
            }
        }
        __syncthreads();

        const int dbase = ((wid >> 1) & 1) * 64;
#pragma unroll
        for (int mi = 0; mi < 4; ++mi) {
            int rl = mi * 16 + g;
            float ss0 = red[wid * 64 + rl]     + red[(wid ^ 2) * 64 + rl];
            float ss1 = red[wid * 64 + rl + 8] + red[(wid ^ 2) * 64 + rl + 8];
            float r0 = rsqrtf(ss0 * (1.f / 128.f) + EPSF) * QSCL;
            float r1 = rsqrtf(ss1 * (1.f / 128.f) + EPSF) * QSCL;
            int row0 = bm + wm * 64 + rl;
#pragma unroll
            for (int nj = 0; nj < 8; ++nj) {
                int d = dbase + nj * 8 + q4 * 2;
                float w0 = nqw[d], w1 = nqw[d + 1];
                size_t c0 = (size_t)row0 * N + bn + wn * 64 + nj * 8 + q4 * 2;
                *(__half2*)(q16 + c0) =
                    __floats2half2_rn(acc[mi][nj][0] * r0 * w0, acc[mi][nj][1] * r0 * w1);
                *(__half2*)(q16 + c0 + (size_t)8 * N) =
                    __floats2half2_rn(acc[mi][nj][2] * r1 * w0, acc[mi][nj][3] * r1 * w1);
            }
        }
    } else {
#pragma unroll
        for (int mi = 0; mi < 4; ++mi) {
            float s0 = 0.f, s1 = 0.f;
#pragma unroll
            for (int nj = 0; nj < 8; ++nj) {
                s0 += acc[mi][nj][0] * acc[mi][nj][0];
                s1 += acc[mi][nj][2] * acc[mi][nj][2];
            }
            s0 += __shfl_xor_sync(0xffffffffu, s0, 1);
            s0 += __shfl_xor_sync(0xffffffffu, s0, 2);
            s1 += __shfl_xor_sync(0xffffffffu, s1, 1);
            s1 += __shfl_xor_sync(0xffffffffu, s1, 2);
            if (q4 == 0) {
                red[wid * 64 + mi * 16 + g]     = s0;
                red[wid * 64 + mi * 16 + g + 8] = s1;
            }
        }
        __syncthreads();

        const int kvh = bnIdx;
#pragma unroll
        for (int mi = 0; mi < 4; ++mi) {
            int rl = mi * 16 + g;
            float ss0 = red[wm * 64 + rl] + red[(2 + wm) * 64 + rl]
                      + red[(4 + wm) * 64 + rl] + red[(6 + wm) * 64 + rl];
            float ss1 = red[wm * 64 + rl + 8] + red[(2 + wm) * 64 + rl + 8]
                      + red[(4 + wm) * 64 + rl + 8] + red[(6 + wm) * 64 + rl + 8];
            float r0 = rsqrtf(ss0 * (1.f / 128.f) + EPSF);
            float r1 = rsqrtf(ss1 * (1.f / 128.f) + EPSF);
            int m0 = bm + wm * 64 + rl;
            int b0 = m0 >> 11, l0 = m0 & 2047;
            size_t base0 = ((size_t)(b0 * NKVH + kvh) * CLEN + l0) * HD;
            size_t base1 = base0 + 8 * HD;
#pragma unroll
            for (int nj = 0; nj < 8; ++nj) {
                int d = wn * 32 + nj * 4 + q4;
                float wk = nkw[d];
                k16[base0 + d] = __float2half_rn(acc[mi][nj][0] * r0 * wk);
                v16[base0 + d] = __float2half_rn(acc[mi][nj][1]);
                k16[base1 + d] = __float2half_rn(acc[mi][nj][2] * r1 * wk);
                v16[base1 + d] = __float2half_rn(acc[mi][nj][3]);
            }
        }
    }
}

// ---------------- fp16 flash attention: BQ=64, 4 warps, occ 2 --------------
#define QPITCH  272
#define QBYTES  (64 * QPITCH)       // 17408
#define KVT     (64 * QPITCH)       // 17408
#define KVSTG   (2 * KVT)           // 34816: K, V
#define ATTN_SMEM (QBYTES + 2 * KVSTG)   // 87040

__global__ __launch_bounds__(128, 2) void attn_f16_kernel(
    const __half* __restrict__ q16, const __half* __restrict__ k16,
    const __half* __restrict__ v16, __half* __restrict__ o16)
{
    extern __shared__ char smc[];
    const uint32_t sb = smem_u32(smc);

    const int tid  = threadIdx.x;
    const int lane = tid & 31;
    const int wid  = tid >> 5;
    const int h    = blockIdx.y;
    const int b    = blockIdx.z;
    const int kvh  = h >> 2;
    const int s0   = blockIdx.x * 64;

    const __half* qg = q16 + ((size_t)(b * SEQ + s0) * NH + h) * HD;
    const size_t kvbase = (size_t)(b * NKVH + kvh) * CLEN * HD;

    {
        int chunk = tid & 15, r0 = tid >> 4;
#pragma unroll
        for (int it = 0; it < 8; ++it) {
            int row = r0 + it * 8;
            cpa16(sb + row * QPITCH + chunk * 16, qg + (size_t)row * HIDDIM + chunk * 8);
        }
        CP_COMMIT();
    }

    auto loadKV = [&](int blk, int stage) {
        uint32_t st = sb + QBYTES + stage * KVSTG;
        const __half* pk = k16 + kvbase + (size_t)blk * 64 * HD;
        const __half* pv = v16 + kvbase + (size_t)blk * 64 * HD;
        int chunk = tid & 15, r0 = tid >> 4;
#pragma unroll
        for (int it = 0; it < 8; ++it) {
            int row = r0 + it * 8;
            uint32_t d = st + row * QPITCH + chunk * 16;
            size_t g = (size_t)row * HD + chunk * 8;
            cpa16(d,       pk + g);
            cpa16(d + KVT, pv + g);
        }
        CP_COMMIT();
    };
    loadKV(0, 0);

    float m0 = -1e30f, m1 = -1e30f, l0 = 0.f, l1 = 0.f;
    float ofr[16][4];
#pragma unroll
    for (int f = 0; f < 16; ++f)
#pragma unroll
        for (int r = 0; r < 4; ++r) ofr[f][r] = 0.f;

    const uint32_t laneOff = (lane & 15) * QPITCH + (lane >> 4) * 16;
    const uint32_t qBase = sb + (wid * 16) * QPITCH + laneOff;

    float scA[8][4], scB[8][4];

#define QK_BLOCK(SC, STG) do {                                                   \
    uint32_t kB_ = sb + QBYTES + (STG) * KVSTG + laneOff;                        \
    _Pragma("unroll")                                                            \
    for (int j = 0; j < 8; ++j) {                                                \
        SC[j][0] = 0.f; SC[j][1] = 0.f; SC[j][2] = 0.f; SC[j][3] = 0.f;          \
    }                                                                            \
    _Pragma("unroll")                                                            \
    for (int kc = 0; kc < 8; ++kc) {                                             \
        uint32_t qa[4];                                                          \
        ldsm4(qa[0], qa[1], qa[2], qa[3], qBase + kc * 32);                      \
        _Pragma("unroll")                                                        \
        for (int kg = 0; kg < 4; ++kg) {                                         \
            uint32_t kb[4];                                                      \
            ldsm4(kb[0], kb[1], kb[2], kb[3], kB_ + kg * 16 * QPITCH + kc * 32); \
            mma16816(SC[kg * 2],     qa, kb[0], kb[2]);                          \
            mma16816(SC[kg * 2 + 1], qa, kb[1], kb[3]);                          \
        }                                                                        \
    }                                                                            \
} while (0)

#define SOFTPV(SC, BLK) do {                                                     \
    float mx0 = -1e30f, mx1 = -1e30f;                                            \
    _Pragma("unroll")                                                            \
    for (int j = 0; j < 8; ++j) {                                                \
        mx0 = fmaxf(mx0, fmaxf(SC[j][0], SC[j][1]));                             \
        mx1 = fmaxf(mx1, fmaxf(SC[j][2], SC[j][3]));                             \
    }                                                                            \
    mx0 = fmaxf(mx0, __shfl_xor_sync(0xffffffffu, mx0, 1));                      \
    mx0 = fmaxf(mx0, __shfl_xor_sync(0xffffffffu, mx0, 2));                      \
    mx1 = fmaxf(mx1, __shfl_xor_sync(0xffffffffu, mx1, 1));                      \
    mx1 = fmaxf(mx1, __shfl_xor_sync(0xffffffffu, mx1, 2));                      \
    float c0_ = ex2f(m0 - fmaxf(m0, mx0)), c1_ = ex2f(m1 - fmaxf(m1, mx1));      \
    m0 = fmaxf(m0, mx0); m1 = fmaxf(m1, mx1);                                    \
    float rs0 = 0.f, rs1 = 0.f;                                                  \
    _Pragma("unroll")                                                            \
    for (int j = 0; j < 8; ++j) {                                                \
        SC[j][0] = ex2f(SC[j][0] - m0); rs0 += SC[j][0];                         \
        SC[j][1] = ex2f(SC[j][1] - m0); rs0 += SC[j][1];                         \
        SC[j][2] = ex2f(SC[j][2] - m1); rs1 += SC[j][2];                         \
        SC[j][3] = ex2f(SC[j][3] - m1); rs1 += SC[j][3];                         \
    }                                                                            \
    rs0 += __shfl_xor_sync(0xffffffffu, rs0, 1);                                 \
    rs0 += __shfl_xor_sync(0xffffffffu, rs0, 2);                                 \
    rs1 += __shfl_xor_sync(0xffffffffu, rs1, 1);                                 \
    rs1 += __shfl_xor_sync(0xffffffffu, rs1, 2);                                 \
    l0 = l0 * c0_ + rs0;                                                         \
    l1 = l1 * c1_ + rs1;                                                         \
    _Pragma("unroll")                                                            \
    for (int f = 0; f < 16; ++f) {                                               \
        ofr[f][0] *= c0_; ofr[f][1] *= c0_;                                      \
        ofr[f][2] *= c1_; ofr[f][3] *= c1_;                                      \
    }                                                                            \
    uint32_t pa[4][4];                                                           \
    _Pragma("unroll")                                                            \
    for (int kc = 0; kc < 4; ++kc) {                                             \
        _Pragma("unroll")                                                        \
        for (int hf = 0; hf < 2; ++hf) {                                         \
            pa[kc][hf * 2]     = packh2(SC[2 * kc + hf][0], SC[2 * kc + hf][1]); \
            pa[kc][hf * 2 + 1] = packh2(SC[2 * kc + hf][2], SC[2 * kc + hf][3]); \
        }                                                                        \
    }                                                                            \
    uint32_t vB_ = sb + QBYTES + ((BLK) & 1) * KVSTG + KVT + laneOff;            \
    _Pragma("unroll")                                                            \
    for (int dg = 0; dg < 8; ++dg) {                                             \
        _Pragma("unroll")                                                        \
        for (int kc = 0; kc < 4; ++kc) {                                         \
            uint32_t vb[4];                                                      \
            ldsm4t(vb[0], vb[1], vb[2], vb[3], vB_ + kc * 16 * QPITCH + dg * 32);\
            mma16816(ofr[dg * 2],     pa[kc], vb[0], vb[1]);                     \
            mma16816(ofr[dg * 2 + 1], pa[kc], vb[2], vb[3]);                     \
        }                                                                        \
    }                                                                            \
} while (0)

    asm volatile("cp.async.wait_group 0;" ::: "memory");
    __syncthreads();
    QK_BLOCK(scA, 0);

#pragma unroll 1
    for (int blk = 0; blk < 32; blk += 2) {
        if (blk + 1 < 32) loadKV(blk + 1, (blk + 1) & 1);
        SOFTPV(scA, blk);
        if (blk + 1 < 32) {
            asm volatile("cp.async.wait_group 0;" ::: "memory");
            __syncthreads();
            QK_BLOCK(scB, (blk + 1) & 1);
        }
        if (blk + 2 < 32) loadKV(blk + 2, (blk + 2) & 1);
        if (blk + 1 < 32) SOFTPV(scB, blk + 1);
        if (blk + 2 < 32) {
            asm volatile("cp.async.wait_group 0;" ::: "memory");
            __syncthreads();
            QK_BLOCK(scA, (blk + 2) & 1);
        }
    }

    float inv0 = 1.f / l0, inv1 = 1.f / l1;
    int rowA = b * SEQ + s0 + wid * 16 + (lane >> 2);
    int colB = h * HD + (lane & 3) * 2;
#pragma unroll
    for (int f = 0; f < 16; ++f) {
        int col = colB + f * 8;
        *(__half2*)(o16 + (size_t)rowA * HIDDIM + col) =
            __floats2half2_rn(ofr[f][0] * inv0, ofr[f][1] * inv0);
        *(__half2*)(o16 + (size_t)(rowA + 8) * HIDDIM + col) =
            __floats2half2_rn(ofr[f][2] * inv1, ofr[f][3] * inv1);
    }
}

// ---------------- launch ----------------------------------------------------
extern "C" void kernel_launch(void* const* d_in, const int* in_sizes, int n_in,
                              void* d_out, int out_size)
{
    (void)in_sizes; (void)n_in; (void)out_size;
    const float* x   = (const float*)d_in[0];
    const float* c   = (const float*)d_in[1];
    const float* wq  = (const float*)d_in[2];
    const float* wkv = (const float*)d_in[3];
    const float* wo  = (const float*)d_in[4];
    const float* nqw = (const float*)d_in[5];
    const float* nkw = (const float*)d_in[6];
    float* out = (float*)d_out;

    __half *x16, *c16, *q16, *k16, *v16, *wqT, *wkvT, *woT;
    cudaGetSymbolAddress((void**)&x16,  g_x16);
    cudaGetSymbolAddress((void**)&c16,  g_c16);
    cudaGetSymbolAddress((void**)&q16,  g_q16);
    cudaGetSymbolAddress((void**)&k16,  g_k16);
    cudaGetSymbolAddress((void**)&v16,  g_v16);
    cudaGetSymbolAddress((void**)&wqT,  g_wqT);
    cudaGetSymbolAddress((void**)&wkvT, g_wkvT);
    cudaGetSymbolAddress((void**)&woT,  g_woT);

    const int M = BATCH * SEQ;            // 4096
    const int K = HIDDIM;                 // 2048
    const int gemm256_smem = NST1 * STB1; // 92160
    cudaFuncSetAttribute(gemm_qkv_fused_kernel,
                         cudaFuncAttributeMaxDynamicSharedMemorySize, gemm256_smem);
    cudaFuncSetAttribute(gemm_o_kernel,
                         cudaFuncAttributeMaxDynamicSharedMemorySize, gemm256_smem);
    cudaFuncSetAttribute(attn_f16_kernel,
                         cudaFuncAttributeMaxDynamicSharedMemorySize, ATTN_SMEM);

    // 0) all conversions in one launch
    prep_kernel<<<26624, 256>>>((const float4*)x, (const float4*)c,
                                wq, wkv, wo, x16, c16, wqT, wkvT, woT);

    // 1) Q-proj + KV-proj in one launch (12 x 32 tiles of 128x256)
    gemm_qkv_fused_kernel<<<dim3(12, M / 128), 256, gemm256_smem>>>(
        x16, wqT, nqw, q16, c16, wkvT, nkw, k16, v16);

    // 2) attention: BQ=64, 4 warps, occ 2 per SM
    attn_f16_kernel<<<dim3(SEQ / 64, NH, BATCH), 128, ATTN_SMEM>>>(
        q16, k16, v16, x16);

    // 3) output projection (128x256, occ 1) -> fp32 out
    gemm_o_kernel<<<dim3(HIDDIM / 256, M / 128), 256, gemm256_smem>>>(
        x16, woT, out, M, HIDDIM, K);
}

// round 14
// speedup vs baseline: 1.0197x; 1.0197x over previous
#include <cuda_runtime.h>
#include <cuda_fp16.h>
#include <math.h>
#include <stdint.h>

#define BATCH 2
#define SEQ   2048
#define CLEN  2048
#define NH    16
#define NKVH  4
#define HD    128
#define HIDDIM 2048
#define EPSF  1e-6f
#define QSCL  (0.08838834764831845f * 1.4426950408889634f)

// ---------------- scratch (device globals) ---------------------------------
__device__ __half g_x16[BATCH*SEQ*HIDDIM];
__device__ __half g_c16[BATCH*SEQ*HIDDIM];
__device__ __half g_q16[BATCH*SEQ*HIDDIM];
__device__ __half g_k16[BATCH*NKVH*CLEN*HD];
__device__ __half g_v16[BATCH*NKVH*CLEN*HD];
__device__ __half g_wqT [HIDDIM*HIDDIM];
__device__ __half g_wkvT[HIDDIM*NKVH*HD*2];
__device__ __half g_woT [HIDDIM*HIDDIM];

// ======================= helpers ============================================
__device__ __forceinline__ uint32_t smem_u32(const void* p) {
    uint32_t a;
    asm("{ .reg .u64 t; cvta.to.shared.u64 t, %1; cvt.u32.u64 %0, t; }" : "=r"(a) : "l"(p));
    return a;
}
__device__ __forceinline__ void cpa16(uint32_t d, const void* g) {
    asm volatile("cp.async.cg.shared.global [%0], [%1], 16;" :: "r"(d), "l"(g) : "memory");
}
#define CP_COMMIT() asm volatile("cp.async.commit_group;" ::: "memory")

__device__ __forceinline__ void ldsm4(uint32_t& r0, uint32_t& r1, uint32_t& r2, uint32_t& r3,
                                      uint32_t a) {
    asm volatile("ldmatrix.sync.aligned.m8n8.x4.shared.b16 {%0,%1,%2,%3}, [%4];"
                 : "=r"(r0), "=r"(r1), "=r"(r2), "=r"(r3) : "r"(a));
}
__device__ __forceinline__ void ldsm4t(uint32_t& r0, uint32_t& r1, uint32_t& r2, uint32_t& r3,
                                       uint32_t a) {
    asm volatile("ldmatrix.sync.aligned.m8n8.x4.trans.shared.b16 {%0,%1,%2,%3}, [%4];"
                 : "=r"(r0), "=r"(r1), "=r"(r2), "=r"(r3) : "r"(a));
}
__device__ __forceinline__ void mma16816(float* c, const uint32_t* a, uint32_t b0, uint32_t b1) {
    asm volatile(
        "mma.sync.aligned.m16n8k16.row.col.f32.f16.f16.f32 "
        "{%0,%1,%2,%3}, {%4,%5,%6,%7}, {%8,%9}, {%0,%1,%2,%3};"
        : "+f"(c[0]), "+f"(c[1]), "+f"(c[2]), "+f"(c[3])
        : "r"(a[0]), "r"(a[1]), "r"(a[2]), "r"(a[3]), "r"(b0), "r"(b1));
}
__device__ __forceinline__ uint32_t packh2(float a, float b) {
    __half2 h = __floats2half2_rn(a, b);
    return *(uint32_t*)&h;
}
__device__ __forceinline__ float ex2f(float x) {
    float y;
    asm("ex2.approx.f32 %0, %1;" : "=f"(y) : "f"(x));
    return y;
}

// ---------------- fused prep kernel -----------------------------------------
#define NF4 ((size_t)BATCH * SEQ * HIDDIM / 4)

__global__ __launch_bounds__(256) void prep_kernel(
    const float4* __restrict__ x, const float4* __restrict__ c,
    const float* __restrict__ wq, const float* __restrict__ wkv,
    const float* __restrict__ wo,
    __half* __restrict__ x16, __half* __restrict__ c16,
    __half* __restrict__ wqT, __half* __restrict__ wkvT, __half* __restrict__ woT)
{
    __shared__ float s[32][33];
    int bid = blockIdx.x;

    if (bid < 16384) {
        size_t i = (size_t)bid * 256 + threadIdx.x;
        const float4* src; __half* dst; size_t j;
        if (i < NF4) { src = x; dst = x16; j = i; }
        else         { src = c; dst = c16; j = i - NF4; }
        float4 v = src[j];
        ((__half2*)dst)[j * 2]     = __floats2half2_rn(v.x, v.y);
        ((__half2*)dst)[j * 2 + 1] = __floats2half2_rn(v.z, v.w);
        return;
    }
    bid -= 16384;

    const float* w; __half* o; int N;
    if (bid < 4096)      {              w = wq;  o = wqT;  N = HIDDIM; }
    else if (bid < 6144) { bid -= 4096; w = wkv; o = wkvT; N = NKVH * HD * 2; }
    else                 { bid -= 6144; w = wo;  o = woT;  N = HIDDIM; }

    const int K = HIDDIM;
    int nb = N / 32;
    int n0 = (bid % nb) * 32, k0 = (bid / nb) * 32;
    int tx = threadIdx.x & 31, ty = threadIdx.x >> 5;
#pragma unroll
    for (int i = ty; i < 32; i += 8)
        s[i][tx] = w[(size_t)(k0 + i) * N + n0 + tx];
    __syncthreads();
#pragma unroll
    for (int j = ty; j < 32; j += 8)
        o[(size_t)(n0 + j) * K + k0 + tx] = __float2half_rn(s[tx][j]);
}

// ============ GEMM mainloop macros (4-stage pipelines) ======================
#define TP2  80
#define A_T  (128 * TP2)             // 10240
#define B_T  (256 * TP2)             // 20480
#define STB1 (A_T + B_T)             // 30720   (128x256 stage)
#define NST1 4                       // 122880 B smem, occ 1
#define B1_T (128 * TP2)
#define STB128 (A_T + B1_T)          // 20480   (128x128 stage)
#define NST2 4                       // 81920 B smem, occ 2

// 128x256 tile mainloop, runtime bn (occ 1, 4 stages, prefetch dist 3)
#define GEMM_MAINLOOP256(APTR, BPTR, BNVAL, KDIM)                                \
    extern __shared__ char smc[];                                                \
    const uint32_t sb = smem_u32(smc);                                           \
    const int tid  = threadIdx.x;                                                \
    const int lane = tid & 31;                                                   \
    const int wid  = tid >> 5;                                                   \
    const int wm   = wid & 1;                                                    \
    const int wn   = wid >> 1;                                                   \
    const int bm   = blockIdx.y * 128;                                           \
    const int bn   = (BNVAL);                                                    \
    const int arow = tid >> 1;                                                   \
    const int ahalf = tid & 1;                                                   \
    const size_t gA = (size_t)(bm + arow) * (KDIM) + ahalf * 16;                 \
    const uint32_t sA = arow * TP2 + ahalf * 32;                                 \
    const size_t gB = (size_t)(bn + tid) * (KDIM);                               \
    const uint32_t sB = tid * TP2;                                               \
    const uint32_t laneOff = (lane & 15) * TP2 + (lane >> 4) * 16;               \
    float acc[4][8][4];                                                          \
    _Pragma("unroll")                                                            \
    for (int i = 0; i < 4; i++)                                                  \
        _Pragma("unroll")                                                        \
        for (int j = 0; j < 8; j++)                                              \
            _Pragma("unroll")                                                    \
            for (int r = 0; r < 4; r++) acc[i][j][r] = 0.f;                      \
    const int nst = (KDIM) / 32;                                                 \
    auto loadStage = [&](int s, int buf) {                                       \
        uint32_t st = sb + buf * STB1;                                           \
        int k0 = s * 32;                                                         \
        cpa16(st + sA,      (APTR) + gA + k0);                                   \
        cpa16(st + sA + 16, (APTR) + gA + k0 + 8);                               \
        uint32_t bb = st + A_T + sB;                                             \
        cpa16(bb,      (BPTR) + gB + k0);                                        \
        cpa16(bb + 16, (BPTR) + gB + k0 + 8);                                    \
        cpa16(bb + 32, (BPTR) + gB + k0 + 16);                                   \
        cpa16(bb + 48, (BPTR) + gB + k0 + 24);                                   \
        CP_COMMIT();                                                             \
    };                                                                           \
    loadStage(0, 0);                                                             \
    loadStage(1, 1);                                                             \
    loadStage(2, 2);                                                             \
    int buf = 0;                                                                 \
    for (int s = 0; s < nst; ++s) {                                              \
        if (s + 2 < nst)      asm volatile("cp.async.wait_group 2;" ::: "memory"); \
        else if (s + 1 < nst) asm volatile("cp.async.wait_group 1;" ::: "memory"); \
        else                  asm volatile("cp.async.wait_group 0;" ::: "memory"); \
        __syncthreads();                                                         \
        if (s + 3 < nst) loadStage(s + 3, (buf + 3) & 3);                        \
        uint32_t st = sb + buf * STB1;                                           \
        uint32_t aBase  = st + (wm * 64) * TP2 + laneOff;                        \
        uint32_t bBase  = st + A_T + (wn * 64) * TP2 + laneOff;                  \
        _Pragma("unroll")                                                        \
        for (int ks = 0; ks < 2; ++ks) {                                         \
            uint32_t ko = ks * 32;                                               \
            uint32_t af[4][4];                                                   \
            _Pragma("unroll")                                                    \
            for (int mi = 0; mi < 4; ++mi)                                       \
                ldsm4(af[mi][0], af[mi][1], af[mi][2], af[mi][3],                \
                      aBase + mi * 16 * TP2 + ko);                               \
            _Pragma("unroll")                                                    \
            for (int bi = 0; bi < 4; ++bi) {                                     \
                uint32_t bf[4];                                                  \
                ldsm4(bf[0], bf[1], bf[2], bf[3], bBase + bi * 16 * TP2 + ko);   \
                _Pragma("unroll")                                                \
                for (int mi = 0; mi < 4; ++mi) {                                 \
                    _Pragma("unroll")                                            \
                    for (int sub = 0; sub < 2; ++sub)                            \
                        mma16816(acc[mi][bi * 2 + sub], af[mi], bf[sub], bf[sub + 2]); \
                }                                                                \
            }                                                                    \
        }                                                                        \
        buf = (buf + 1) & 3;                                                     \
        __syncthreads();                                                         \
    }

// 128x128 tile mainloop (occ 2, 4 stages, prefetch dist 3) — O-projection
#define GEMM_MAINLOOP128(APTR, BPTR, KDIM)                                       \
    extern __shared__ char smc[];                                                \
    const uint32_t sb = smem_u32(smc);                                           \
    const int tid  = threadIdx.x;                                                \
    const int lane = tid & 31;                                                   \
    const int wid  = tid >> 5;                                                   \
    const int wm   = wid & 1;                                                    \
    const int wn   = wid >> 1;                                                   \
    const int bm   = blockIdx.y * 128;                                           \
    const int bn   = blockIdx.x * 128;                                           \
    const int arow = tid >> 1;                                                   \
    const int ahalf = tid & 1;                                                   \
    const size_t gA = (size_t)(bm + arow) * (KDIM) + ahalf * 16;                 \
    const size_t gB = (size_t)(bn + arow) * (KDIM) + ahalf * 16;                 \
    const uint32_t sA = arow * TP2 + ahalf * 32;                                 \
    const uint32_t laneOff = (lane & 15) * TP2 + (lane >> 4) * 16;               \
    float acc[4][4][4];                                                          \
    _Pragma("unroll")                                                            \
    for (int i = 0; i < 4; i++)                                                  \
        _Pragma("unroll")                                                        \
        for (int j = 0; j < 4; j++)                                              \
            _Pragma("unroll")                                                    \
            for (int r = 0; r < 4; r++) acc[i][j][r] = 0.f;                      \
    const int nst = (KDIM) / 32;                                                 \
    auto loadStage = [&](int s, int buf) {                                       \
        uint32_t st = sb + buf * STB128;                                         \
        int k0 = s * 32;                                                         \
        cpa16(st + sA,            (APTR) + gA + k0);                             \
        cpa16(st + sA + 16,       (APTR) + gA + k0 + 8);                         \
        cpa16(st + A_T + sA,      (BPTR) + gB + k0);                             \
        cpa16(st + A_T + sA + 16, (BPTR) + gB + k0 + 8);                         \
        CP_COMMIT();                                                             \
    };                                                                           \
    loadStage(0, 0);                                                             \
    loadStage(1, 1);                                                             \
    loadStage(2, 2);                                                             \
    int buf = 0;                                                                 \
    for (int s = 0; s < nst; ++s) {                                              \
        if (s + 2 < nst)      asm volatile("cp.async.wait_group 2;" ::: "memory"); \
        else if (s + 1 < nst) asm volatile("cp.async.wait_group 1;" ::: "memory"); \
        else                  asm volatile("cp.async.wait_group 0;" ::: "memory"); \
        __syncthreads();                                                         \
        if (s + 3 < nst) loadStage(s + 3, (buf + 3) & 3);                        \
        uint32_t st = sb + buf * STB128;                                         \
        uint32_t aBase  = st + (wm * 64) * TP2 + laneOff;                        \
        uint32_t bBase  = st + A_T + (wn * 32) * TP2 + laneOff;                  \
        _Pragma("unroll")                                                        \
        for (int ks = 0; ks < 2; ++ks) {                                         \
            uint32_t ko = ks * 32;                                               \
            uint32_t af[4][4];                                                   \
            _Pragma("unroll")                                                    \
            for (int mi = 0; mi < 4; ++mi)                                       \
                ldsm4(af[mi][0], af[mi][1], af[mi][2], af[mi][3],                \
                      aBase + mi * 16 * TP2 + ko);                               \
            _Pragma("unroll")                                                    \
            for (int bi = 0; bi < 2; ++bi) {                                     \
                uint32_t bf[4];                                                  \
                ldsm4(bf[0], bf[1], bf[2], bf[3], bBase + bi * 16 * TP2 + ko);   \
                _Pragma("unroll")                                                \
                for (int mi = 0; mi < 4; ++mi) {                                 \
                    _Pragma("unroll")                                            \
                    for (int sub = 0; sub < 2; ++sub)                            \
                        mma16816(acc[mi][bi * 2 + sub], af[mi], bf[sub], bf[sub + 2]); \
                }                                                                \
            }                                                                    \
        }                                                                        \
        buf = (buf + 1) & 3;                                                     \
        __syncthreads();                                                         \
    }

// ---------------- O-projection GEMM (128x128, occ 2, fp32 out) -------------
__global__ __launch_bounds__(256, 2) void gemm_o_kernel(
    const __half* __restrict__ A, const __half* __restrict__ Bh,
    float* __restrict__ C, int M, int N, int K)
{
    GEMM_MAINLOOP128(A, Bh, K)
    const int g  = lane >> 2;
    const int q4 = lane & 3;
#pragma unroll
    for (int mi = 0; mi < 4; ++mi) {
#pragma unroll
        for (int nj = 0; nj < 4; ++nj) {
            int r0 = bm + wm * 64 + mi * 16 + g;
            int c0 = bn + wn * 32 + nj * 8 + q4 * 2;
            *(float2*)(C + (size_t)r0 * N + c0)       = make_float2(acc[mi][nj][0], acc[mi][nj][1]);
            *(float2*)(C + (size_t)(r0 + 8) * N + c0) = make_float2(acc[mi][nj][2], acc[mi][nj][3]);
        }
    }
}

// ---------------- unified Q-proj + KV-proj GEMM (128x256, occ 1) -----------
__global__ __launch_bounds__(256, 1) void gemm_qkv_fused_kernel(
    const __half* __restrict__ x16a, const __half* __restrict__ wqT,
    const float* __restrict__ nqw, __half* __restrict__ q16,
    const __half* __restrict__ c16a, const __half* __restrict__ wkvT,
    const float* __restrict__ nkw, __half* __restrict__ k16,
    __half* __restrict__ v16)
{
    const bool isQ = blockIdx.x < 8;
    const __half* Ap = isQ ? x16a : c16a;
    const __half* Bp = isQ ? wqT : wkvT;
    const int bnIdx = isQ ? blockIdx.x : blockIdx.x - 8;

    GEMM_MAINLOOP256(Ap, Bp, bnIdx * 256, HIDDIM)

    float* red = (float*)smc;
    const int g  = lane >> 2;
    const int q4 = lane & 3;

    if (isQ) {
        const int N = HIDDIM;
#pragma unroll
        for (int mi = 0; mi < 4; ++mi) {
            float s0 = 0.f, s1 = 0.f;
#pragma unroll
            for (int nj = 0; nj < 8; ++nj) {
                s0 += acc[mi][nj][0] * acc[mi][nj][0] + acc[mi][nj][1] * acc[mi][nj][1];
                s1 += acc[mi][nj][2] * acc[mi][nj][2] + acc[mi][nj][3] * acc[mi][nj][3];
            }
            s0 += __shfl_xor_sync(0xffffffffu, s0, 1);
            s0 += __shfl_xor_sync(0xffffffffu, s0, 2);
            s1 += __shfl_xor_sync(0xffffffffu, s1, 1);
            s1 += __shfl_xor_sync(0xffffffffu, s1, 2);
            if (q4 == 0) {
                red[wid * 64 + mi * 16 + g]     = s0;
                red[wid * 64 + mi * 16 + g + 8] = s1;
            }
        }
        __syncthreads();

        const int dbase = ((wid >> 1) & 1) * 64;
#pragma unroll
        for (int mi = 0; mi < 4; ++mi) {
            int rl = mi * 16 + g;
            float ss0 = red[wid * 64 + rl]     + red[(wid ^ 2) * 64 + rl];
            float ss1 = red[wid * 64 + rl + 8] + red[(wid ^ 2) * 64 + rl + 8];
            float r0 = rsqrtf(ss0 * (1.f / 128.f) + EPSF) * QSCL;
            float r1 = rsqrtf(ss1 * (1.f / 128.f) + EPSF) * QSCL;
            int row0 = bm + wm * 64 + rl;
#pragma unroll
            for (int nj = 0; nj < 8; ++nj) {
                int d = dbase + nj * 8 + q4 * 2;
                float w0 = nqw[d], w1 = nqw[d + 1];
                size_t c0 = (size_t)row0 * N + bn + wn * 64 + nj * 8 + q4 * 2;
                *(__half2*)(q16 + c0) =
                    __floats2half2_rn(acc[mi][nj][0] * r0 * w0, acc[mi][nj][1] * r0 * w1);
                *(__half2*)(q16 + c0 + (size_t)8 * N) =
                    __floats2half2_rn(acc[mi][nj][2] * r1 * w0, acc[mi][nj][3] * r1 * w1);
            }
        }
    } else {
#pragma unroll
        for (int mi = 0; mi < 4; ++mi) {
            float s0 = 0.f, s1 = 0.f;
#pragma unroll
            for (int nj = 0; nj < 8; ++nj) {
                s0 += acc[mi][nj][0] * acc[mi][nj][0];
                s1 += acc[mi][nj][2] * acc[mi][nj][2];
            }
            s0 += __shfl_xor_sync(0xffffffffu, s0, 1);
            s0 += __shfl_xor_sync(0xffffffffu, s0, 2);
            s1 += __shfl_xor_sync(0xffffffffu, s1, 1);
            s1 += __shfl_xor_sync(0xffffffffu, s1, 2);
            if (q4 == 0) {
                red[wid * 64 + mi * 16 + g]     = s0;
                red[wid * 64 + mi * 16 + g + 8] = s1;
            }
        }
        __syncthreads();

        const int kvh = bnIdx;
#pragma unroll
        for (int mi = 0; mi < 4; ++mi) {
            int rl = mi * 16 + g;
            float ss0 = red[wm * 64 + rl] + red[(2 + wm) * 64 + rl]
                      + red[(4 + wm) * 64 + rl] + red[(6 + wm) * 64 + rl];
            float ss1 = red[wm * 64 + rl + 8] + red[(2 + wm) * 64 + rl + 8]
                      + red[(4 + wm) * 64 + rl + 8] + red[(6 + wm) * 64 + rl + 8];
            float r0 = rsqrtf(ss0 * (1.f / 128.f) + EPSF);
            float r1 = rsqrtf(ss1 * (1.f / 128.f) + EPSF);
            int m0 = bm + wm * 64 + rl;
            int b0 = m0 >> 11, l0 = m0 & 2047;
            size_t base0 = ((size_t)(b0 * NKVH + kvh) * CLEN + l0) * HD;
            size_t base1 = base0 + 8 * HD;
#pragma unroll
            for (int nj = 0; nj < 8; ++nj) {
                int d = wn * 32 + nj * 4 + q4;
                float wk = nkw[d];
                k16[base0 + d] = __float2half_rn(acc[mi][nj][0] * r0 * wk);
                v16[base0 + d] = __float2half_rn(acc[mi][nj][1]);
                k16[base1 + d] = __float2half_rn(acc[mi][nj][2] * r1 * wk);
                v16[base1 + d] = __float2half_rn(acc[mi][nj][3]);
            }
        }
    }
}

// ---------------- fp16 flash attention: BQ=64, 4 warps, occ 2 --------------
#define QPITCH  272
#define QBYTES  (64 * QPITCH)       // 17408
#define KVT     (64 * QPITCH)       // 17408
#define KVSTG   (2 * KVT)           // 34816: K, V
#define ATTN_SMEM (QBYTES + 2 * KVSTG)   // 87040

__global__ __launch_bounds__(128, 2) void attn_f16_kernel(
    const __half* __restrict__ q16, const __half* __restrict__ k16,
    const __half* __restrict__ v16, __half* __restrict__ o16)
{
    extern __shared__ char smc[];
    const uint32_t sb = smem_u32(smc);

    const int tid  = threadIdx.x;
    const int lane = tid & 31;
    const int wid  = tid >> 5;
    const int h    = blockIdx.y;
    const int b    = blockIdx.z;
    const int kvh  = h >> 2;
    const int s0   = blockIdx.x * 64;

    const __half* qg = q16 + ((size_t)(b * SEQ + s0) * NH + h) * HD;
    const size_t kvbase = (size_t)(b * NKVH + kvh) * CLEN * HD;

    {
        int chunk = tid & 15, r0 = tid >> 4;
#pragma unroll
        for (int it = 0; it < 8; ++it) {
            int row = r0 + it * 8;
            cpa16(sb + row * QPITCH + chunk * 16, qg + (size_t)row * HIDDIM + chunk * 8);
        }
        CP_COMMIT();
    }

    auto loadKV = [&](int blk, int stage) {
        uint32_t st = sb + QBYTES + stage * KVSTG;
        const __half* pk = k16 + kvbase + (size_t)blk * 64 * HD;
        const __half* pv = v16 + kvbase + (size_t)blk * 64 * HD;
        int chunk = tid & 15, r0 = tid >> 4;
#pragma unroll
        for (int it = 0; it < 8; ++it) {
            int row = r0 + it * 8;
            uint32_t d = st + row * QPITCH + chunk * 16;
            size_t g = (size_t)row * HD + chunk * 8;
            cpa16(d,       pk + g);
            cpa16(d + KVT, pv + g);
        }
        CP_COMMIT();
    };
    loadKV(0, 0);

    float m0 = -1e30f, m1 = -1e30f, l0 = 0.f, l1 = 0.f;
    float ofr[16][4];
#pragma unroll
    for (int f = 0; f < 16; ++f)
#pragma unroll
        for (int r = 0; r < 4; ++r) ofr[f][r] = 0.f;

    const uint32_t laneOff = (lane & 15) * QPITCH + (lane >> 4) * 16;
    const uint32_t qBase = sb + (wid * 16) * QPITCH + laneOff;

    float scA[8][4], scB[8][4];

#define QK_BLOCK(SC, STG) do {                                                   \
    uint32_t kB_ = sb + QBYTES + (STG) * KVSTG + laneOff;                        \
    _Pragma("unroll")                                                            \
    for (int j = 0; j < 8; ++j) {                                                \
        SC[j][0] = 0.f; SC[j][1] = 0.f; SC[j][2] = 0.f; SC[j][3] = 0.f;          \
    }                                                                            \
    _Pragma("unroll")                                                            \
    for (int kc = 0; kc < 8; ++kc) {                                             \
        uint32_t qa[4];                                                          \
        ldsm4(qa[0], qa[1], qa[2], qa[3], qBase + kc * 32);                      \
        _Pragma("unroll")                                                        \
        for (int kg = 0; kg < 4; ++kg) {                                         \
            uint32_t kb[4];                                                      \
            ldsm4(kb[0], kb[1], kb[2], kb[3], kB_ + kg * 16 * QPITCH + kc * 32); \
            mma16816(SC[kg * 2],     qa, kb[0], kb[2]);                          \
            mma16816(SC[kg * 2 + 1], qa, kb[1], kb[3]);                          \
        }                                                                        \
    }                                                                            \
} while (0)

#define SOFTPV(SC, BLK) do {                                                     \
    float mx0 = -1e30f, mx1 = -1e30f;                                            \
    _Pragma("unroll")                                                            \
    for (int j = 0; j < 8; ++j) {                                                \
        mx0 = fmaxf(mx0, fmaxf(SC[j][0], SC[j][1]));                             \
        mx1 = fmaxf(mx1, fmaxf(SC[j][2], SC[j][3]));                             \
    }                                                                            \
    mx0 = fmaxf(mx0, __shfl_xor_sync(0xffffffffu, mx0, 1));                      \
    mx0 = fmaxf(mx0, __shfl_xor_sync(0xffffffffu, mx0, 2));                      \
    mx1 = fmaxf(mx1, __shfl_xor_sync(0xffffffffu, mx1, 1));                      \
    mx1 = fmaxf(mx1, __shfl_xor_sync(0xffffffffu, mx1, 2));                      \
    float c0_ = ex2f(m0 - fmaxf(m0, mx0)), c1_ = ex2f(m1 - fmaxf(m1, mx1));      \
    m0 = fmaxf(m0, mx0); m1 = fmaxf(m1, mx1);                                    \
    float rs0 = 0.f, rs1 = 0.f;                                                  \
    _Pragma("unroll")                                                            \
    for (int j = 0; j < 8; ++j) {                                                \
        SC[j][0] = ex2f(SC[j][0] - m0); rs0 += SC[j][0];                         \
        SC[j][1] = ex2f(SC[j][1] - m0); rs0 += SC[j][1];                         \
        SC[j][2] = ex2f(SC[j][2] - m1); rs1 += SC[j][2];                         \
        SC[j][3] = ex2f(SC[j][3] - m1); rs1 += SC[j][3];                         \
    }                                                                            \
    rs0 += __shfl_xor_sync(0xffffffffu, rs0, 1);                                 \
    rs0 += __shfl_xor_sync(0xffffffffu, rs0, 2);                                 \
    rs1 += __shfl_xor_sync(0xffffffffu, rs1, 1);                                 \
    rs1 += __shfl_xor_sync(0xffffffffu, rs1, 2);                                 \
    l0 = l0 * c0_ + rs0;                                                         \
    l1 = l1 * c1_ + rs1;                                                         \
    _Pragma("unroll")                                                            \
    for (int f = 0; f < 16; ++f) {                                               \
        ofr[f][0] *= c0_; ofr[f][1] *= c0_;                                      \
        ofr[f][2] *= c1_; ofr[f][3] *= c1_;                                      \
    }                                                                            \
    uint32_t pa[4][4];                                                           \
    _Pragma("unroll")                                                            \
    for (int kc = 0; kc < 4; ++kc) {                                             \
        _Pragma("unroll")                                                        \
        for (int hf = 0; hf < 2; ++hf) {                                         \
            pa[kc][hf * 2]     = packh2(SC[2 * kc + hf][0], SC[2 * kc + hf][1]); \
            pa[kc][hf * 2 + 1] = packh2(SC[2 * kc + hf][2], SC[2 * kc + hf][3]); \
        }                                                                        \
    }                                                                            \
    uint32_t vB_ = sb + QBYTES + ((BLK) & 1) * KVSTG + KVT + laneOff;            \
    _Pragma("unroll")                                                            \
    for (int dg = 0; dg < 8; ++dg) {                                             \
        _Pragma("unroll")                                                        \
        for (int kc = 0; kc < 4; ++kc) {                                         \
            uint32_t vb[4];                                                      \
            ldsm4t(vb[0], vb[1], vb[2], vb[3], vB_ + kc * 16 * QPITCH + dg * 32);\
            mma16816(ofr[dg * 2],     pa[kc], vb[0], vb[1]);                     \
            mma16816(ofr[dg * 2 + 1], pa[kc], vb[2], vb[3]);                     \
        }                                                                        \
    }                                                                            \
} while (0)

    asm volatile("cp.async.wait_group 0;" ::: "memory");
    __syncthreads();
    QK_BLOCK(scA, 0);

#pragma unroll 1
    for (int blk = 0; blk < 32; blk += 2) {
        if (blk + 1 < 32) loadKV(blk + 1, (blk + 1) & 1);
        SOFTPV(scA, blk);
        if (blk + 1 < 32) {
            asm volatile("cp.async.wait_group 0;" ::: "memory");
            __syncthreads();
            QK_BLOCK(scB, (blk + 1) & 1);
        }
        if (blk + 2 < 32) loadKV(blk + 2, (blk + 2) & 1);
        if (blk + 1 < 32) SOFTPV(scB, blk + 1);
        if (blk + 2 < 32) {
            asm volatile("cp.async.wait_group 0;" ::: "memory");
            __syncthreads();
            QK_BLOCK(scA, (blk + 2) & 1);
        }
    }

    float inv0 = 1.f / l0, inv1 = 1.f / l1;
    int rowA = b * SEQ + s0 + wid * 16 + (lane >> 2);
    int colB = h * HD + (lane & 3) * 2;
#pragma unroll
    for (int f = 0; f < 16; ++f) {
        int col = colB + f * 8;
        *(__half2*)(o16 + (size_t)rowA * HIDDIM + col) =
            __floats2half2_rn(ofr[f][0] * inv0, ofr[f][1] * inv0);
        *(__half2*)(o16 + (size_t)(rowA + 8) * HIDDIM + col) =
            __floats2half2_rn(ofr[f][2] * inv1, ofr[f][3] * inv1);
    }
}

// ---------------- launch ----------------------------------------------------
extern "C" void kernel_launch(void* const* d_in, const int* in_sizes, int n_in,
                              void* d_out, int out_size)
{
    (void)in_sizes; (void)n_in; (void)out_size;
    const float* x   = (const float*)d_in[0];
    const float* c   = (const float*)d_in[1];
    const float* wq  = (const float*)d_in[2];
    const float* wkv = (const float*)d_in[3];
    const float* wo  = (const float*)d_in[4];
    const float* nqw = (const float*)d_in[5];
    const float* nkw = (const float*)d_in[6];
    float* out = (float*)d_out;

    __half *x16, *c16, *q16, *k16, *v16, *wqT, *wkvT, *woT;
    cudaGetSymbolAddress((void**)&x16,  g_x16);
    cudaGetSymbolAddress((void**)&c16,  g_c16);
    cudaGetSymbolAddress((void**)&q16,  g_q16);
    cudaGetSymbolAddress((void**)&k16,  g_k16);
    cudaGetSymbolAddress((void**)&v16,  g_v16);
    cudaGetSymbolAddress((void**)&wqT,  g_wqT);
    cudaGetSymbolAddress((void**)&wkvT, g_wkvT);
    cudaGetSymbolAddress((void**)&woT,  g_woT);

    const int M = BATCH * SEQ;            // 4096
    const int K = HIDDIM;                 // 2048
    const int gemm256_smem = NST1 * STB1; // 122880
    const int gemm128_smem = NST2 * STB128; // 81920
    cudaFuncSetAttribute(gemm_qkv_fused_kernel,
                         cudaFuncAttributeMaxDynamicSharedMemorySize, gemm256_smem);
    cudaFuncSetAttribute(gemm_o_kernel,
                         cudaFuncAttributeMaxDynamicSharedMemorySize, gemm128_smem);
    cudaFuncSetAttribute(attn_f16_kernel,
                         cudaFuncAttributeMaxDynamicSharedMemorySize, ATTN_SMEM);

    // 0) all conversions in one launch
    prep_kernel<<<26624, 256>>>((const float4*)x, (const float4*)c,
                                wq, wkv, wo, x16, c16, wqT, wkvT, woT);

    // 1) Q-proj + KV-proj in one launch (12 x 32 tiles of 128x256, 4-stage)
    gemm_qkv_fused_kernel<<<dim3(12, M / 128), 256, gemm256_smem>>>(
        x16, wqT, nqw, q16, c16, wkvT, nkw, k16, v16);

    // 2) attention: BQ=64, 4 warps, occ 2 per SM
    attn_f16_kernel<<<dim3(SEQ / 64, NH, BATCH), 128, ATTN_SMEM>>>(
        q16, k16, v16, x16);

    // 3) output projection (128x128, occ 2, 4-stage) -> fp32 out
    gemm_o_kernel<<<dim3(HIDDIM / 128, M / 128), 256, gemm128_smem>>>(
        x16, woT, out, M, HIDDIM, K);
}

// round 15
// speedup vs baseline: 1.0428x; 1.0227x over previous
#include <cuda_runtime.h>
#include <cuda_fp16.h>
#include <math.h>
#include <stdint.h>

#define BATCH 2
#define SEQ   2048
#define CLEN  2048
#define NH    16
#define NKVH  4
#define HD    128
#define HIDDIM 2048
#define EPSF  1e-6f
#define QSCL  (0.08838834764831845f * 1.4426950408889634f)

// ---------------- scratch (device globals) ---------------------------------
__device__ __half g_x16[BATCH*SEQ*HIDDIM];
__device__ __half g_c16[BATCH*SEQ*HIDDIM];
__device__ __half g_q16[BATCH*SEQ*HIDDIM];
__device__ __half g_k16[BATCH*NKVH*CLEN*HD];
__device__ __half g_v16[BATCH*NKVH*CLEN*HD];
__device__ __half g_wqT [HIDDIM*HIDDIM];
__device__ __half g_wkvT[HIDDIM*NKVH*HD*2];
__device__ __half g_woT [HIDDIM*HIDDIM];

// ======================= helpers ============================================
__device__ __forceinline__ uint32_t smem_u32(const void* p) {
    uint32_t a;
    asm("{ .reg .u64 t; cvta.to.shared.u64 t, %1; cvt.u32.u64 %0, t; }" : "=r"(a) : "l"(p));
    return a;
}
__device__ __forceinline__ void cpa16(uint32_t d, const void* g) {
    asm volatile("cp.async.cg.shared.global [%0], [%1], 16;" :: "r"(d), "l"(g) : "memory");
}
#define CP_COMMIT() asm volatile("cp.async.commit_group;" ::: "memory")

__device__ __forceinline__ void ldsm4(uint32_t& r0, uint32_t& r1, uint32_t& r2, uint32_t& r3,
                                      uint32_t a) {
    asm volatile("ldmatrix.sync.aligned.m8n8.x4.shared.b16 {%0,%1,%2,%3}, [%4];"
                 : "=r"(r0), "=r"(r1), "=r"(r2), "=r"(r3) : "r"(a));
}
__device__ __forceinline__ void ldsm4t(uint32_t& r0, uint32_t& r1, uint32_t& r2, uint32_t& r3,
                                       uint32_t a) {
    asm volatile("ldmatrix.sync.aligned.m8n8.x4.trans.shared.b16 {%0,%1,%2,%3}, [%4];"
                 : "=r"(r0), "=r"(r1), "=r"(r2), "=r"(r3) : "r"(a));
}
__device__ __forceinline__ void mma16816(float* c, const uint32_t* a, uint32_t b0, uint32_t b1) {
    asm volatile(
        "mma.sync.aligned.m16n8k16.row.col.f32.f16.f16.f32 "
        "{%0,%1,%2,%3}, {%4,%5,%6,%7}, {%8,%9}, {%0,%1,%2,%3};"
        : "+f"(c[0]), "+f"(c[1]), "+f"(c[2]), "+f"(c[3])
        : "r"(a[0]), "r"(a[1]), "r"(a[2]), "r"(a[3]), "r"(b0), "r"(b1));
}
__device__ __forceinline__ uint32_t packh2(float a, float b) {
    __half2 h = __floats2half2_rn(a, b);
    return *(uint32_t*)&h;
}
__device__ __forceinline__ float ex2f(float x) {
    float y;
    asm("ex2.approx.f32 %0, %1;" : "=f"(y) : "f"(x));
    return y;
}

// ---------------- fused prep kernel -----------------------------------------
#define NF4 ((size_t)BATCH * SEQ * HIDDIM / 4)

__global__ __launch_bounds__(256) void prep_kernel(
    const float4* __restrict__ x, const float4* __restrict__ c,
    const float* __restrict__ wq, const float* __restrict__ wkv,
    const float* __restrict__ wo,
    __half* __restrict__ x16, __half* __restrict__ c16,
    __half* __restrict__ wqT, __half* __restrict__ wkvT, __half* __restrict__ woT)
{
    __shared__ float s[32][33];
    int bid = blockIdx.x;

    if (bid < 16384) {
        size_t i = (size_t)bid * 256 + threadIdx.x;
        const float4* src; __half* dst; size_t j;
        if (i < NF4) { src = x; dst = x16; j = i; }
        else         { src = c; dst = c16; j = i - NF4; }
        float4 v = src[j];
        ((__half2*)dst)[j * 2]     = __floats2half2_rn(v.x, v.y);
        ((__half2*)dst)[j * 2 + 1] = __floats2half2_rn(v.z, v.w);
        return;
    }
    bid -= 16384;

    const float* w; __half* o; int N;
    if (bid < 4096)      {              w = wq;  o = wqT;  N = HIDDIM; }
    else if (bid < 6144) { bid -= 4096; w = wkv; o = wkvT; N = NKVH * HD * 2; }
    else                 { bid -= 6144; w = wo;  o = woT;  N = HIDDIM; }

    const int K = HIDDIM;
    int nb = N / 32;
    int n0 = (bid % nb) * 32, k0 = (bid / nb) * 32;
    int tx = threadIdx.x & 31, ty = threadIdx.x >> 5;
#pragma unroll
    for (int i = ty; i < 32; i += 8)
        s[i][tx] = w[(size_t)(k0 + i) * N + n0 + tx];
    __syncthreads();
#pragma unroll
    for (int j = ty; j < 32; j += 8)
        o[(size_t)(n0 + j) * K + k0 + tx] = __float2half_rn(s[tx][j]);
}

// ============ GEMM mainloop macros (3-stage, R12 config) ====================
#define TP2  80
#define A_T  (128 * TP2)             // 10240
#define B_T  (256 * TP2)             // 20480
#define STB1 (A_T + B_T)             // 30720  (128x256)
#define NST1 3
#define B1_T (128 * TP2)
#define STB128 (A_T + B1_T)          // 20480  (128x128)

// 128x256 tile mainloop, runtime bn (occ 1)
#define GEMM_MAINLOOP256(APTR, BPTR, BNVAL, KDIM)                                \
    extern __shared__ char smc[];                                                \
    const uint32_t sb = smem_u32(smc);                                           \
    const int tid  = threadIdx.x;                                                \
    const int lane = tid & 31;                                                   \
    const int wid  = tid >> 5;                                                   \
    const int wm   = wid & 1;                                                    \
    const int wn   = wid >> 1;                                                   \
    const int bm   = blockIdx.y * 128;                                           \
    const int bn   = (BNVAL);                                                    \
    const int arow = tid >> 1;                                                   \
    const int ahalf = tid & 1;                                                   \
    const size_t gA = (size_t)(bm + arow) * (KDIM) + ahalf * 16;                 \
    const uint32_t sA = arow * TP2 + ahalf * 32;                                 \
    const size_t gB = (size_t)(bn + tid) * (KDIM);                               \
    const uint32_t sB = tid * TP2;                                               \
    const uint32_t laneOff = (lane & 15) * TP2 + (lane >> 4) * 16;               \
    float acc[4][8][4];                                                          \
    _Pragma("unroll")                                                            \
    for (int i = 0; i < 4; i++)                                                  \
        _Pragma("unroll")                                                        \
        for (int j = 0; j < 8; j++)                                              \
            _Pragma("unroll")                                                    \
            for (int r = 0; r < 4; r++) acc[i][j][r] = 0.f;                      \
    const int nst = (KDIM) / 32;                                                 \
    auto loadStage = [&](int s, int buf) {                                       \
        uint32_t st = sb + buf * STB1;                                           \
        int k0 = s * 32;                                                         \
        cpa16(st + sA,      (APTR) + gA + k0);                                   \
        cpa16(st + sA + 16, (APTR) + gA + k0 + 8);                               \
        uint32_t bb = st + A_T + sB;                                             \
        cpa16(bb,      (BPTR) + gB + k0);                                        \
        cpa16(bb + 16, (BPTR) + gB + k0 + 8);                                    \
        cpa16(bb + 32, (BPTR) + gB + k0 + 16);                                   \
        cpa16(bb + 48, (BPTR) + gB + k0 + 24);                                   \
        CP_COMMIT();                                                             \
    };                                                                           \
    loadStage(0, 0);                                                             \
    loadStage(1, 1);                                                             \
    int buf = 0;                                                                 \
    for (int s = 0; s < nst; ++s) {                                              \
        if (s + 1 < nst) asm volatile("cp.async.wait_group 1;" ::: "memory");    \
        else             asm volatile("cp.async.wait_group 0;" ::: "memory");    \
        __syncthreads();                                                         \
        if (s + 2 < nst) loadStage(s + 2, (buf + 2) % NST1);                     \
        uint32_t st = sb + buf * STB1;                                           \
        uint32_t aBase  = st + (wm * 64) * TP2 + laneOff;                        \
        uint32_t bBase  = st + A_T + (wn * 64) * TP2 + laneOff;                  \
        _Pragma("unroll")                                                        \
        for (int ks = 0; ks < 2; ++ks) {                                         \
            uint32_t ko = ks * 32;                                               \
            uint32_t af[4][4];                                                   \
            _Pragma("unroll")                                                    \
            for (int mi = 0; mi < 4; ++mi)                                       \
                ldsm4(af[mi][0], af[mi][1], af[mi][2], af[mi][3],                \
                      aBase + mi * 16 * TP2 + ko);                               \
            _Pragma("unroll")                                                    \
            for (int bi = 0; bi < 4; ++bi) {                                     \
                uint32_t bf[4];                                                  \
                ldsm4(bf[0], bf[1], bf[2], bf[3], bBase + bi * 16 * TP2 + ko);   \
                _Pragma("unroll")                                                \
                for (int mi = 0; mi < 4; ++mi) {                                 \
                    _Pragma("unroll")                                            \
                    for (int sub = 0; sub < 2; ++sub)                            \
                        mma16816(acc[mi][bi * 2 + sub], af[mi], bf[sub], bf[sub + 2]); \
                }                                                                \
            }                                                                    \
        }                                                                        \
        buf = (buf + 1) % NST1;                                                  \
        __syncthreads();                                                         \
    }

// 128x128 tile mainloop (occ 2) — Q-proj and O-proj
#define GEMM_MAINLOOP128(APTR, BPTR, KDIM)                                       \
    extern __shared__ char smc[];                                                \
    const uint32_t sb = smem_u32(smc);                                           \
    const int tid  = threadIdx.x;                                                \
    const int lane = tid & 31;                                                   \
    const int wid  = tid >> 5;                                                   \
    const int wm   = wid & 1;                                                    \
    const int wn   = wid >> 1;                                                   \
    const int bm   = blockIdx.y * 128;                                           \
    const int bn   = blockIdx.x * 128;                                           \
    const int arow = tid >> 1;                                                   \
    const int ahalf = tid & 1;                                                   \
    const size_t gA = (size_t)(bm + arow) * (KDIM) + ahalf * 16;                 \
    const size_t gB = (size_t)(bn + arow) * (KDIM) + ahalf * 16;                 \
    const uint32_t sA = arow * TP2 + ahalf * 32;                                 \
    const uint32_t laneOff = (lane & 15) * TP2 + (lane >> 4) * 16;               \
    float acc[4][4][4];                                                          \
    _Pragma("unroll")                                                            \
    for (int i = 0; i < 4; i++)                                                  \
        _Pragma("unroll")                                                        \
        for (int j = 0; j < 4; j++)                                              \
            _Pragma("unroll")                                                    \
            for (int r = 0; r < 4; r++) acc[i][j][r] = 0.f;                      \
    const int nst = (KDIM) / 32;                                                 \
    auto loadStage = [&](int s, int buf) {                                       \
        uint32_t st = sb + buf * STB128;                                         \
        int k0 = s * 32;                                                         \
        cpa16(st + sA,            (APTR) + gA + k0);                             \
        cpa16(st + sA + 16,       (APTR) + gA + k0 + 8);                         \
        cpa16(st + A_T + sA,      (BPTR) + gB + k0);                             \
        cpa16(st + A_T + sA + 16, (BPTR) + gB + k0 + 8);                         \
        CP_COMMIT();                                                             \
    };                                                                           \
    loadStage(0, 0);                                                             \
    loadStage(1, 1);                                                             \
    int buf = 0;                                                                 \
    for (int s = 0; s < nst; ++s) {                                              \
        if (s + 1 < nst) asm volatile("cp.async.wait_group 1;" ::: "memory");    \
        else             asm volatile("cp.async.wait_group 0;" ::: "memory");    \
        __syncthreads();                                                         \
        if (s + 2 < nst) loadStage(s + 2, (buf + 2) % 3);                        \
        uint32_t st = sb + buf * STB128;                                         \
        uint32_t aBase  = st + (wm * 64) * TP2 + laneOff;                        \
        uint32_t bBase  = st + A_T + (wn * 32) * TP2 + laneOff;                  \
        _Pragma("unroll")                                                        \
        for (int ks = 0; ks < 2; ++ks) {                                         \
            uint32_t ko = ks * 32;                                               \
            uint32_t af[4][4];                                                   \
            _Pragma("unroll")                                                    \
            for (int mi = 0; mi < 4; ++mi)                                       \
                ldsm4(af[mi][0], af[mi][1], af[mi][2], af[mi][3],                \
                      aBase + mi * 16 * TP2 + ko);                               \
            _Pragma("unroll")                                                    \
            for (int bi = 0; bi < 2; ++bi) {                                     \
                uint32_t bf[4];                                                  \
                ldsm4(bf[0], bf[1], bf[2], bf[3], bBase + bi * 16 * TP2 + ko);   \
                _Pragma("unroll")                                                \
                for (int mi = 0; mi < 4; ++mi) {                                 \
                    _Pragma("unroll")                                            \
                    for (int sub = 0; sub < 2; ++sub)                            \
                        mma16816(acc[mi][bi * 2 + sub], af[mi], bf[sub], bf[sub + 2]); \
                }                                                                \
            }                                                                    \
        }                                                                        \
        buf = (buf + 1) % 3;                                                     \
        __syncthreads();                                                         \
    }

// ---------------- O-projection GEMM (128x128, occ 2, fp32 out) -------------
__global__ __launch_bounds__(256, 2) void gemm_o_kernel(
    const __half* __restrict__ A, const __half* __restrict__ Bh,
    float* __restrict__ C, int M, int N, int K)
{
    GEMM_MAINLOOP128(A, Bh, K)
    const int g  = lane >> 2;
    const int q4 = lane & 3;
#pragma unroll
    for (int mi = 0; mi < 4; ++mi) {
#pragma unroll
        for (int nj = 0; nj < 4; ++nj) {
            int r0 = bm + wm * 64 + mi * 16 + g;
            int c0 = bn + wn * 32 + nj * 8 + q4 * 2;
            *(float2*)(C + (size_t)r0 * N + c0)       = make_float2(acc[mi][nj][0], acc[mi][nj][1]);
            *(float2*)(C + (size_t)(r0 + 8) * N + c0) = make_float2(acc[mi][nj][2], acc[mi][nj][3]);
        }
    }
}

// ---------------- Q-proj GEMM (128x128, occ 2) + fused RMSNorm + scale -----
// One tile = one head (128 cols): reduce across the 4 N-warps.
__global__ __launch_bounds__(256, 2) void gemm_q_fused_kernel(
    const __half* __restrict__ A, const __half* __restrict__ Bh,
    const float* __restrict__ nqw, __half* __restrict__ q16, int M, int N, int K)
{
    GEMM_MAINLOOP128(A, Bh, K)
    float* red = (float*)smc;   // 8 warps x 64 rows
    const int g  = lane >> 2;
    const int q4 = lane & 3;
#pragma unroll
    for (int mi = 0; mi < 4; ++mi) {
        float s0 = 0.f, s1 = 0.f;
#pragma unroll
        for (int nj = 0; nj < 4; ++nj) {
            s0 += acc[mi][nj][0] * acc[mi][nj][0] + acc[mi][nj][1] * acc[mi][nj][1];
            s1 += acc[mi][nj][2] * acc[mi][nj][2] + acc[mi][nj][3] * acc[mi][nj][3];
        }
        s0 += __shfl_xor_sync(0xffffffffu, s0, 1);
        s0 += __shfl_xor_sync(0xffffffffu, s0, 2);
        s1 += __shfl_xor_sync(0xffffffffu, s1, 1);
        s1 += __shfl_xor_sync(0xffffffffu, s1, 2);
        if (q4 == 0) {
            red[wid * 64 + mi * 16 + g]     = s0;
            red[wid * 64 + mi * 16 + g + 8] = s1;
        }
    }
    __syncthreads();

#pragma unroll
    for (int mi = 0; mi < 4; ++mi) {
        int rl = mi * 16 + g;
        float ss0 = red[wm * 64 + rl] + red[(2 + wm) * 64 + rl]
                  + red[(4 + wm) * 64 + rl] + red[(6 + wm) * 64 + rl];
        float ss1 = red[wm * 64 + rl + 8] + red[(2 + wm) * 64 + rl + 8]
                  + red[(4 + wm) * 64 + rl + 8] + red[(6 + wm) * 64 + rl + 8];
        float r0 = rsqrtf(ss0 * (1.f / 128.f) + EPSF) * QSCL;
        float r1 = rsqrtf(ss1 * (1.f / 128.f) + EPSF) * QSCL;
        int row0 = bm + wm * 64 + rl;
#pragma unroll
        for (int nj = 0; nj < 4; ++nj) {
            int d = wn * 32 + nj * 8 + q4 * 2;
            float w0 = nqw[d], w1 = nqw[d + 1];
            size_t c0 = (size_t)row0 * N + bn + d;
            *(__half2*)(q16 + c0) =
                __floats2half2_rn(acc[mi][nj][0] * r0 * w0, acc[mi][nj][1] * r0 * w1);
            *(__half2*)(q16 + c0 + (size_t)8 * N) =
                __floats2half2_rn(acc[mi][nj][2] * r1 * w0, acc[mi][nj][3] * r1 * w1);
        }
    }
}

// ---------------- KV-proj GEMM (128x256, occ 1) + fused split/K-norm -------
__global__ __launch_bounds__(256, 1) void gemm_kv_fused_kernel(
    const __half* __restrict__ A, const __half* __restrict__ Bh,
    const float* __restrict__ nkw, __half* __restrict__ k16,
    __half* __restrict__ v16)
{
    GEMM_MAINLOOP256(A, Bh, blockIdx.x * 256, HIDDIM)
    float* red = (float*)smc;
    const int g  = lane >> 2;
    const int q4 = lane & 3;
#pragma unroll
    for (int mi = 0; mi < 4; ++mi) {
        float s0 = 0.f, s1 = 0.f;
#pragma unroll
        for (int nj = 0; nj < 8; ++nj) {
            s0 += acc[mi][nj][0] * acc[mi][nj][0];
            s1 += acc[mi][nj][2] * acc[mi][nj][2];
        }
        s0 += __shfl_xor_sync(0xffffffffu, s0, 1);
        s0 += __shfl_xor_sync(0xffffffffu, s0, 2);
        s1 += __shfl_xor_sync(0xffffffffu, s1, 1);
        s1 += __shfl_xor_sync(0xffffffffu, s1, 2);
        if (q4 == 0) {
            red[wid * 64 + mi * 16 + g]     = s0;
            red[wid * 64 + mi * 16 + g + 8] = s1;
        }
    }
    __syncthreads();

    const int kvh = blockIdx.x;
#pragma unroll
    for (int mi = 0; mi < 4; ++mi) {
        int rl = mi * 16 + g;
        float ss0 = red[wm * 64 + rl] + red[(2 + wm) * 64 + rl]
                  + red[(4 + wm) * 64 + rl] + red[(6 + wm) * 64 + rl];
        float ss1 = red[wm * 64 + rl + 8] + red[(2 + wm) * 64 + rl + 8]
                  + red[(4 + wm) * 64 + rl + 8] + red[(6 + wm) * 64 + rl + 8];
        float r0 = rsqrtf(ss0 * (1.f / 128.f) + EPSF);
        float r1 = rsqrtf(ss1 * (1.f / 128.f) + EPSF);
        int m0 = bm + wm * 64 + rl;
        int b0 = m0 >> 11, l0 = m0 & 2047;
        size_t base0 = ((size_t)(b0 * NKVH + kvh) * CLEN + l0) * HD;
        size_t base1 = base0 + 8 * HD;
#pragma unroll
        for (int nj = 0; nj < 8; ++nj) {
            int d = wn * 32 + nj * 4 + q4;
            float wk = nkw[d];
            k16[base0 + d] = __float2half_rn(acc[mi][nj][0] * r0 * wk);
            v16[base0 + d] = __float2half_rn(acc[mi][nj][1]);
            k16[base1 + d] = __float2half_rn(acc[mi][nj][2] * r1 * wk);
            v16[base1 + d] = __float2half_rn(acc[mi][nj][3]);
        }
    }
}

// ---------------- fp16 flash attention: BQ=64, 4 warps, occ 2 --------------
#define QPITCH  272
#define QBYTES  (64 * QPITCH)       // 17408
#define KVT     (64 * QPITCH)       // 17408
#define KVSTG   (2 * KVT)           // 34816: K, V
#define ATTN_SMEM (QBYTES + 2 * KVSTG)   // 87040

__global__ __launch_bounds__(128, 2) void attn_f16_kernel(
    const __half* __restrict__ q16, const __half* __restrict__ k16,
    const __half* __restrict__ v16, __half* __restrict__ o16)
{
    extern __shared__ char smc[];
    const uint32_t sb = smem_u32(smc);

    const int tid  = threadIdx.x;
    const int lane = tid & 31;
    const int wid  = tid >> 5;
    const int h    = blockIdx.y;
    const int b    = blockIdx.z;
    const int kvh  = h >> 2;
    const int s0   = blockIdx.x * 64;

    const __half* qg = q16 + ((size_t)(b * SEQ + s0) * NH + h) * HD;
    const size_t kvbase = (size_t)(b * NKVH + kvh) * CLEN * HD;

    {
        int chunk = tid & 15, r0 = tid >> 4;
#pragma unroll
        for (int it = 0; it < 8; ++it) {
            int row = r0 + it * 8;
            cpa16(sb + row * QPITCH + chunk * 16, qg + (size_t)row * HIDDIM + chunk * 8);
        }
        CP_COMMIT();
    }

    auto loadKV = [&](int blk, int stage) {
        uint32_t st = sb + QBYTES + stage * KVSTG;
        const __half* pk = k16 + kvbase + (size_t)blk * 64 * HD;
        const __half* pv = v16 + kvbase + (size_t)blk * 64 * HD;
        int chunk = tid & 15, r0 = tid >> 4;
#pragma unroll
        for (int it = 0; it < 8; ++it) {
            int row = r0 + it * 8;
            uint32_t d = st + row * QPITCH + chunk * 16;
            size_t g = (size_t)row * HD + chunk * 8;
            cpa16(d,       pk + g);
            cpa16(d + KVT, pv + g);
        }
        CP_COMMIT();
    };
    loadKV(0, 0);

    float m0 = -1e30f, m1 = -1e30f, l0 = 0.f, l1 = 0.f;
    float ofr[16][4];
#pragma unroll
    for (int f = 0; f < 16; ++f)
#pragma unroll
        for (int r = 0; r < 4; ++r) ofr[f][r] = 0.f;

    const uint32_t laneOff = (lane & 15) * QPITCH + (lane >> 4) * 16;
    const uint32_t qBase = sb + (wid * 16) * QPITCH + laneOff;

    float scA[8][4], scB[8][4];

#define QK_BLOCK(SC, STG) do {                                                   \
    uint32_t kB_ = sb + QBYTES + (STG) * KVSTG + laneOff;                        \
    _Pragma("unroll")                                                            \
    for (int j = 0; j < 8; ++j) {                                                \
        SC[j][0] = 0.f; SC[j][1] = 0.f; SC[j][2] = 0.f; SC[j][3] = 0.f;          \
    }                                                                            \
    _Pragma("unroll")                                                            \
    for (int kc = 0; kc < 8; ++kc) {                                             \
        uint32_t qa[4];                                                          \
        ldsm4(qa[0], qa[1], qa[2], qa[3], qBase + kc * 32);                      \
        _Pragma("unroll")                                                        \
        for (int kg = 0; kg < 4; ++kg) {                                         \
            uint32_t kb[4];                                                      \
            ldsm4(kb[0], kb[1], kb[2], kb[3], kB_ + kg * 16 * QPITCH + kc * 32); \
            mma16816(SC[kg * 2],     qa, kb[0], kb[2]);                          \
            mma16816(SC[kg * 2 + 1], qa, kb[1], kb[3]);                          \
        }                                                                        \
    }                                                                            \
} while (0)

#define SOFTPV(SC, BLK) do {                                                     \
    float mx0 = -1e30f, mx1 = -1e30f;                                            \
    _Pragma("unroll")                                                            \
    for (int j = 0; j < 8; ++j) {                                                \
        mx0 = fmaxf(mx0, fmaxf(SC[j][0], SC[j][1]));                             \
        mx1 = fmaxf(mx1, fmaxf(SC[j][2], SC[j][3]));                             \
    }                                                                            \
    mx0 = fmaxf(mx0, __shfl_xor_sync(0xffffffffu, mx0, 1));                      \
    mx0 = fmaxf(mx0, __shfl_xor_sync(0xffffffffu, mx0, 2));                      \
    mx1 = fmaxf(mx1, __shfl_xor_sync(0xffffffffu, mx1, 1));                      \
    mx1 = fmaxf(mx1, __shfl_xor_sync(0xffffffffu, mx1, 2));                      \
    float c0_ = ex2f(m0 - fmaxf(m0, mx0)), c1_ = ex2f(m1 - fmaxf(m1, mx1));      \
    m0 = fmaxf(m0, mx0); m1 = fmaxf(m1, mx1);                                    \
    float rs0 = 0.f, rs1 = 0.f;                                                  \
    _Pragma("unroll")                                                            \
    for (int j = 0; j < 8; ++j) {                                                \
        SC[j][0] = ex2f(SC[j][0] - m0); rs0 += SC[j][0];                         \
        SC[j][1] = ex2f(SC[j][1] - m0); rs0 += SC[j][1];                         \
        SC[j][2] = ex2f(SC[j][2] - m1); rs1 += SC[j][2];                         \
        SC[j][3] = ex2f(SC[j][3] - m1); rs1 += SC[j][3];                         \
    }                                                                            \
    rs0 += __shfl_xor_sync(0xffffffffu, rs0, 1);                                 \
    rs0 += __shfl_xor_sync(0xffffffffu, rs0, 2);                                 \
    rs1 += __shfl_xor_sync(0xffffffffu, rs1, 1);                                 \
    rs1 += __shfl_xor_sync(0xffffffffu, rs1, 2);                                 \
    l0 = l0 * c0_ + rs0;                                                         \
    l1 = l1 * c1_ + rs1;                                                         \
    _Pragma("unroll")                                                            \
    for (int f = 0; f < 16; ++f) {                                               \
        ofr[f][0] *= c0_; ofr[f][1] *= c0_;                                      \
        ofr[f][2] *= c1_; ofr[f][3] *= c1_;                                      \
    }                                                                            \
    uint32_t pa[4][4];                                                           \
    _Pragma("unroll")                                                            \
    for (int kc = 0; kc < 4; ++kc) {                                             \
        _Pragma("unroll")                                                        \
        for (int hf = 0; hf < 2; ++hf) {                                         \
            pa[kc][hf * 2]     = packh2(SC[2 * kc + hf][0], SC[2 * kc + hf][1]); \
            pa[kc][hf * 2 + 1] = packh2(SC[2 * kc + hf][2], SC[2 * kc + hf][3]); \
        }                                                                        \
    }                                                                            \
    uint32_t vB_ = sb + QBYTES + ((BLK) & 1) * KVSTG + KVT + laneOff;            \
    _Pragma("unroll")                                                            \
    for (int dg = 0; dg < 8; ++dg) {                                             \
        _Pragma("unroll")                                                        \
        for (int kc = 0; kc < 4; ++kc) {                                         \
            uint32_t vb[4];                                                      \
            ldsm4t(vb[0], vb[1], vb[2], vb[3], vB_ + kc * 16 * QPITCH + dg * 32);\
            mma16816(ofr[dg * 2],     pa[kc], vb[0], vb[1]);                     \
            mma16816(ofr[dg * 2 + 1], pa[kc], vb[2], vb[3]);                     \
        }                                                                        \
    }                                                                            \
} while (0)

    asm volatile("cp.async.wait_group 0;" ::: "memory");
    __syncthreads();
    QK_BLOCK(scA, 0);

#pragma unroll 1
    for (int blk = 0; blk < 32; blk += 2) {
        if (blk + 1 < 32) loadKV(blk + 1, (blk + 1) & 1);
        SOFTPV(scA, blk);
        if (blk + 1 < 32) {
            asm volatile("cp.async.wait_group 0;" ::: "memory");
            __syncthreads();
            QK_BLOCK(scB, (blk + 1) & 1);
        }
        if (blk + 2 < 32) loadKV(blk + 2, (blk + 2) & 1);
        if (blk + 1 < 32) SOFTPV(scB, blk + 1);
        if (blk + 2 < 32) {
            asm volatile("cp.async.wait_group 0;" ::: "memory");
            __syncthreads();
            QK_BLOCK(scA, (blk + 2) & 1);
        }
    }

    float inv0 = 1.f / l0, inv1 = 1.f / l1;
    int rowA = b * SEQ + s0 + wid * 16 + (lane >> 2);
    int colB = h * HD + (lane & 3) * 2;
#pragma unroll
    for (int f = 0; f < 16; ++f) {
        int col = colB + f * 8;
        *(__half2*)(o16 + (size_t)rowA * HIDDIM + col) =
            __floats2half2_rn(ofr[f][0] * inv0, ofr[f][1] * inv0);
        *(__half2*)(o16 + (size_t)(rowA + 8) * HIDDIM + col) =
            __floats2half2_rn(ofr[f][2] * inv1, ofr[f][3] * inv1);
    }
}

// ---------------- launch ----------------------------------------------------
extern "C" void kernel_launch(void* const* d_in, const int* in_sizes, int n_in,
                              void* d_out, int out_size)
{
    (void)in_sizes; (void)n_in; (void)out_size;
    const float* x   = (const float*)d_in[0];
    const float* c   = (const float*)d_in[1];
    const float* wq  = (const float*)d_in[2];
    const float* wkv = (const float*)d_in[3];
    const float* wo  = (const float*)d_in[4];
    const float* nqw = (const float*)d_in[5];
    const float* nkw = (const float*)d_in[6];
    float* out = (float*)d_out;

    __half *x16, *c16, *q16, *k16, *v16, *wqT, *wkvT, *woT;
    cudaGetSymbolAddress((void**)&x16,  g_x16);
    cudaGetSymbolAddress((void**)&c16,  g_c16);
    cudaGetSymbolAddress((void**)&q16,  g_q16);
    cudaGetSymbolAddress((void**)&k16,  g_k16);
    cudaGetSymbolAddress((void**)&v16,  g_v16);
    cudaGetSymbolAddress((void**)&wqT,  g_wqT);
    cudaGetSymbolAddress((void**)&wkvT, g_wkvT);
    cudaGetSymbolAddress((void**)&woT,  g_woT);

    const int M = BATCH * SEQ;            // 4096
    const int K = HIDDIM;                 // 2048
    const int gemm256_smem = NST1 * STB1; // 92160
    const int gemm128_smem = 3 * STB128;  // 61440
    cudaFuncSetAttribute(gemm_q_fused_kernel,
                         cudaFuncAttributeMaxDynamicSharedMemorySize, gemm128_smem);
    cudaFuncSetAttribute(gemm_kv_fused_kernel,
                         cudaFuncAttributeMaxDynamicSharedMemorySize, gemm256_smem);
    cudaFuncSetAttribute(gemm_o_kernel,
                         cudaFuncAttributeMaxDynamicSharedMemorySize, gemm128_smem);
    cudaFuncSetAttribute(attn_f16_kernel,
                         cudaFuncAttributeMaxDynamicSharedMemorySize, ATTN_SMEM);

    // 0) all conversions in one launch
    prep_kernel<<<26624, 256>>>((const float4*)x, (const float4*)c,
                                wq, wkv, wo, x16, c16, wqT, wkvT, woT);

    // 1) Q projection + fused rmsnorm (128x128, occ 2, 512 CTAs)
    gemm_q_fused_kernel<<<dim3(HIDDIM / 128, M / 128), 256, gemm128_smem>>>(
        x16, wqT, nqw, q16, M, HIDDIM, K);

    // 2) KV projection + fused split/K-rmsnorm (128x256, occ 1, 128 CTAs)
    gemm_kv_fused_kernel<<<dim3(4, M / 128), 256, gemm256_smem>>>(
        c16, wkvT, nkw, k16, v16);

    // 3) attention: BQ=64, 4 warps, occ 2 per SM
    attn_f16_kernel<<<dim3(SEQ / 64, NH, BATCH), 128, ATTN_SMEM>>>(
        q16, k16, v16, x16);

    // 4) output projection (128x128, occ 2) -> fp32 out
    gemm_o_kernel<<<dim3(HIDDIM / 128, M / 128), 256, gemm128_smem>>>(
        x16, woT, out, M, HIDDIM, K);
}

// round 16
// speedup vs baseline: 1.0705x; 1.0266x over previous
#include <cuda_runtime.h>
#include <cuda_fp16.h>
#include <math.h>
#include <stdint.h>

#define BATCH 2
#define SEQ   2048
#define CLEN  2048
#define NH    16
#define NKVH  4
#define HD    128
#define HIDDIM 2048
#define EPSF  1e-6f
#define QSCL  (0.08838834764831845f * 1.4426950408889634f)

// ---------------- scratch (device globals) ---------------------------------
__device__ __half g_x16[BATCH*SEQ*HIDDIM];
__device__ __half g_c16[BATCH*SEQ*HIDDIM];
__device__ __half g_q16[BATCH*SEQ*HIDDIM];
__device__ __half g_k16[BATCH*NKVH*CLEN*HD];
__device__ __half g_v16[BATCH*NKVH*CLEN*HD];
__device__ __half g_wqT [HIDDIM*HIDDIM];
__device__ __half g_wkvT[HIDDIM*NKVH*HD*2];   // de-interleaved: rows [0,512)=K, [512,1024)=V
__device__ __half g_woT [HIDDIM*HIDDIM];

// ======================= helpers ============================================
__device__ __forceinline__ uint32_t smem_u32(const void* p) {
    uint32_t a;
    asm("{ .reg .u64 t; cvta.to.shared.u64 t, %1; cvt.u32.u64 %0, t; }" : "=r"(a) : "l"(p));
    return a;
}
__device__ __forceinline__ void cpa16(uint32_t d, const void* g) {
    asm volatile("cp.async.cg.shared.global [%0], [%1], 16;" :: "r"(d), "l"(g) : "memory");
}
#define CP_COMMIT() asm volatile("cp.async.commit_group;" ::: "memory")

__device__ __forceinline__ void ldsm4(uint32_t& r0, uint32_t& r1, uint32_t& r2, uint32_t& r3,
                                      uint32_t a) {
    asm volatile("ldmatrix.sync.aligned.m8n8.x4.shared.b16 {%0,%1,%2,%3}, [%4];"
                 : "=r"(r0), "=r"(r1), "=r"(r2), "=r"(r3) : "r"(a));
}
__device__ __forceinline__ void ldsm4t(uint32_t& r0, uint32_t& r1, uint32_t& r2, uint32_t& r3,
                                       uint32_t a) {
    asm volatile("ldmatrix.sync.aligned.m8n8.x4.trans.shared.b16 {%0,%1,%2,%3}, [%4];"
                 : "=r"(r0), "=r"(r1), "=r"(r2), "=r"(r3) : "r"(a));
}
__device__ __forceinline__ void mma16816(float* c, const uint32_t* a, uint32_t b0, uint32_t b1) {
    asm volatile(
        "mma.sync.aligned.m16n8k16.row.col.f32.f16.f16.f32 "
        "{%0,%1,%2,%3}, {%4,%5,%6,%7}, {%8,%9}, {%0,%1,%2,%3};"
        : "+f"(c[0]), "+f"(c[1]), "+f"(c[2]), "+f"(c[3])
        : "r"(a[0]), "r"(a[1]), "r"(a[2]), "r"(a[3]), "r"(b0), "r"(b1));
}
__device__ __forceinline__ uint32_t packh2(float a, float b) {
    __half2 h = __floats2half2_rn(a, b);
    return *(uint32_t*)&h;
}
__device__ __forceinline__ float ex2f(float x) {
    float y;
    asm("ex2.approx.f32 %0, %1;" : "=f"(y) : "f"(x));
    return y;
}

// ---------------- fused prep kernel -----------------------------------------
#define NF4 ((size_t)BATCH * SEQ * HIDDIM / 4)

__global__ __launch_bounds__(256) void prep_kernel(
    const float4* __restrict__ x, const float4* __restrict__ c,
    const float* __restrict__ wq, const float* __restrict__ wkv,
    const float* __restrict__ wo,
    __half* __restrict__ x16, __half* __restrict__ c16,
    __half* __restrict__ wqT, __half* __restrict__ wkvT, __half* __restrict__ woT)
{
    __shared__ float s[32][33];
    int bid = blockIdx.x;

    if (bid < 16384) {
        size_t i = (size_t)bid * 256 + threadIdx.x;
        const float4* src; __half* dst; size_t j;
        if (i < NF4) { src = x; dst = x16; j = i; }
        else         { src = c; dst = c16; j = i - NF4; }
        float4 v = src[j];
        ((__half2*)dst)[j * 2]     = __floats2half2_rn(v.x, v.y);
        ((__half2*)dst)[j * 2 + 1] = __floats2half2_rn(v.z, v.w);
        return;
    }
    bid -= 16384;

    const float* w; __half* o; int N; bool dekv = false;
    if (bid < 4096)      {              w = wq;  o = wqT;  N = HIDDIM; }
    else if (bid < 6144) { bid -= 4096; w = wkv; o = wkvT; N = NKVH * HD * 2; dekv = true; }
    else                 { bid -= 6144; w = wo;  o = woT;  N = HIDDIM; }

    const int K = HIDDIM;
    int nb = N / 32;
    int n0 = (bid % nb) * 32, k0 = (bid / nb) * 32;
    int tx = threadIdx.x & 31, ty = threadIdx.x >> 5;
#pragma unroll
    for (int i = ty; i < 32; i += 8)
        s[i][tx] = w[(size_t)(k0 + i) * N + n0 + tx];
    __syncthreads();
#pragma unroll
    for (int j = ty; j < 32; j += 8) {
        int n = n0 + j;
        int row = n;
        if (dekv)   // de-interleave packed KV: K rows first, then V rows
            row = (n >> 8) * 128 + ((n & 255) >> 1) + (n & 1) * 512;
        o[(size_t)row * K + k0 + tx] = __float2half_rn(s[tx][j]);
    }
}

// ============ GEMM mainloop macro (128x128 tile, occ 2, 3-stage) ============
// BPTR must be pre-offset to the tile's first row.
#define TP2  80
#define A_T  (128 * TP2)             // 10240
#define B1_T (128 * TP2)
#define STB128 (A_T + B1_T)          // 20480

#define GEMM_MAINLOOP128(APTR, BPTR, KDIM)                                       \
    extern __shared__ char smc[];                                                \
    const uint32_t sb = smem_u32(smc);                                           \
    const int tid  = threadIdx.x;                                                \
    const int lane = tid & 31;                                                   \
    const int wid  = tid >> 5;                                                   \
    const int wm   = wid & 1;                                                    \
    const int wn   = wid >> 1;                                                   \
    const int bm   = blockIdx.y * 128;                                           \
    const int arow = tid >> 1;                                                   \
    const int ahalf = tid & 1;                                                   \
    const size_t gA = (size_t)(bm + arow) * (KDIM) + ahalf * 16;                 \
    const size_t gB = (size_t)arow * (KDIM) + ahalf * 16;                        \
    const uint32_t sA = arow * TP2 + ahalf * 32;                                 \
    const uint32_t laneOff = (lane & 15) * TP2 + (lane >> 4) * 16;               \
    float acc[4][4][4];                                                          \
    _Pragma("unroll")                                                            \
    for (int i = 0; i < 4; i++)                                                  \
        _Pragma("unroll")                                                        \
        for (int j = 0; j < 4; j++)                                              \
            _Pragma("unroll")                                                    \
            for (int r = 0; r < 4; r++) acc[i][j][r] = 0.f;                      \
    const int nst = (KDIM) / 32;                                                 \
    auto loadStage = [&](int s, int buf) {                                       \
        uint32_t st = sb + buf * STB128;                                         \
        int k0 = s * 32;                                                         \
        cpa16(st + sA,            (APTR) + gA + k0);                             \
        cpa16(st + sA + 16,       (APTR) + gA + k0 + 8);                         \
        cpa16(st + A_T + sA,      (BPTR) + gB + k0);                             \
        cpa16(st + A_T + sA + 16, (BPTR) + gB + k0 + 8);                         \
        CP_COMMIT();                                                             \
    };                                                                           \
    loadStage(0, 0);                                                             \
    loadStage(1, 1);                                                             \
    int buf = 0;                                                                 \
    for (int s = 0; s < nst; ++s) {                                              \
        if (s + 1 < nst) asm volatile("cp.async.wait_group 1;" ::: "memory");    \
        else             asm volatile("cp.async.wait_group 0;" ::: "memory");    \
        __syncthreads();                                                         \
        if (s + 2 < nst) loadStage(s + 2, (buf + 2) % 3);                        \
        uint32_t st = sb + buf * STB128;                                         \
        uint32_t aBase  = st + (wm * 64) * TP2 + laneOff;                        \
        uint32_t bBase  = st + A_T + (wn * 32) * TP2 + laneOff;                  \
        _Pragma("unroll")                                                        \
        for (int ks = 0; ks < 2; ++ks) {                                         \
            uint32_t ko = ks * 32;                                               \
            uint32_t af[4][4];                                                   \
            _Pragma("unroll")                                                    \
            for (int mi = 0; mi < 4; ++mi)                                       \
                ldsm4(af[mi][0], af[mi][1], af[mi][2], af[mi][3],                \
                      aBase + mi * 16 * TP2 + ko);                               \
            _Pragma("unroll")                                                    \
            for (int bi = 0; bi < 2; ++bi) {                                     \
                uint32_t bf[4];                                                  \
                ldsm4(bf[0], bf[1], bf[2], bf[3], bBase + bi * 16 * TP2 + ko);   \
                _Pragma("unroll")                                                \
                for (int mi = 0; mi < 4; ++mi) {                                 \
                    _Pragma("unroll")                                            \
                    for (int sub = 0; sub < 2; ++sub)                            \
                        mma16816(acc[mi][bi * 2 + sub], af[mi], bf[sub], bf[sub + 2]); \
                }                                                                \
            }                                                                    \
        }                                                                        \
        buf = (buf + 1) % 3;                                                     \
        __syncthreads();                                                         \
    }

// ---------------- O-projection GEMM (128x128, occ 2, fp32 out) -------------
__global__ __launch_bounds__(256, 2) void gemm_o_kernel(
    const __half* __restrict__ A, const __half* __restrict__ Bh,
    float* __restrict__ C, int M, int N, int K)
{
    const __half* Bp = Bh + (size_t)blockIdx.x * 128 * K;
    GEMM_MAINLOOP128(A, Bp, K)
    const int bn = blockIdx.x * 128;
    const int g  = lane >> 2;
    const int q4 = lane & 3;
#pragma unroll
    for (int mi = 0; mi < 4; ++mi) {
#pragma unroll
        for (int nj = 0; nj < 4; ++nj) {
            int r0 = bm + wm * 64 + mi * 16 + g;
            int c0 = bn + wn * 32 + nj * 8 + q4 * 2;
            *(float2*)(C + (size_t)r0 * N + c0)       = make_float2(acc[mi][nj][0], acc[mi][nj][1]);
            *(float2*)(C + (size_t)(r0 + 8) * N + c0) = make_float2(acc[mi][nj][2], acc[mi][nj][3]);
        }
    }
}

// ---------------- unified Q/K/V projection (128x128, occ 2) ----------------
// blockIdx.x: [0,16) Q heads; [16,20) K heads; [20,24) V heads.
__global__ __launch_bounds__(256, 2) void gemm_qkv128_kernel(
    const __half* __restrict__ x16a, const __half* __restrict__ wqT,
    const float* __restrict__ nqw, __half* __restrict__ q16,
    const __half* __restrict__ c16a, const __half* __restrict__ wkvT,
    const float* __restrict__ nkw, __half* __restrict__ k16,
    __half* __restrict__ v16)
{
    const int bx = blockIdx.x;
    const int role = (bx < 16) ? 0 : (bx < 20 ? 1 : 2);
    const __half* Ap = (role == 0) ? x16a : c16a;
    const __half* Bp;
    if (role == 0)      Bp = wqT  + (size_t)bx * 128 * HIDDIM;
    else if (role == 1) Bp = wkvT + (size_t)(bx - 16) * 128 * HIDDIM;
    else                Bp = wkvT + (size_t)(512 + (bx - 20) * 128) * HIDDIM;

    GEMM_MAINLOOP128(Ap, Bp, HIDDIM)

    const int g  = lane >> 2;
    const int q4 = lane & 3;

    if (role == 2) {
        // V head: plain fp16 convert into [b][kvh][l][d]
        const int kvh = bx - 20;
#pragma unroll
        for (int mi = 0; mi < 4; ++mi) {
            int m0v = bm + wm * 64 + mi * 16 + g;
            int b0 = m0v >> 11, l0v = m0v & 2047;
            size_t base0 = ((size_t)(b0 * NKVH + kvh) * CLEN + l0v) * HD;
            size_t base1 = base0 + 8 * HD;
#pragma unroll
            for (int nj = 0; nj < 4; ++nj) {
                int d = wn * 32 + nj * 8 + q4 * 2;
                *(__half2*)(v16 + base0 + d) =
                    __floats2half2_rn(acc[mi][nj][0], acc[mi][nj][1]);
                *(__half2*)(v16 + base1 + d) =
                    __floats2half2_rn(acc[mi][nj][2], acc[mi][nj][3]);
            }
        }
        return;
    }

    // Q or K head: per-row RMSNorm over this tile's 128 columns
    float* red = (float*)smc;
#pragma unroll
    for (int mi = 0; mi < 4; ++mi) {
        float s0 = 0.f, s1 = 0.f;
#pragma unroll
        for (int nj = 0; nj < 4; ++nj) {
            s0 += acc[mi][nj][0] * acc[mi][nj][0] + acc[mi][nj][1] * acc[mi][nj][1];
            s1 += acc[mi][nj][2] * acc[mi][nj][2] + acc[mi][nj][3] * acc[mi][nj][3];
        }
        s0 += __shfl_xor_sync(0xffffffffu, s0, 1);
        s0 += __shfl_xor_sync(0xffffffffu, s0, 2);
        s1 += __shfl_xor_sync(0xffffffffu, s1, 1);
        s1 += __shfl_xor_sync(0xffffffffu, s1, 2);
        if (q4 == 0) {
            red[wid * 64 + mi * 16 + g]     = s0;
            red[wid * 64 + mi * 16 + g + 8] = s1;
        }
    }
    __syncthreads();

    const float scl = (role == 0) ? QSCL : 1.f;
    const float* nw = (role == 0) ? nqw : nkw;
#pragma unroll
    for (int mi = 0; mi < 4; ++mi) {
        int rl = mi * 16 + g;
        float ss0 = red[wm * 64 + rl] + red[(2 + wm) * 64 + rl]
                  + red[(4 + wm) * 64 + rl] + red[(6 + wm) * 64 + rl];
        float ss1 = red[wm * 64 + rl + 8] + red[(2 + wm) * 64 + rl + 8]
                  + red[(4 + wm) * 64 + rl + 8] + red[(6 + wm) * 64 + rl + 8];
        float r0 = rsqrtf(ss0 * (1.f / 128.f) + EPSF) * scl;
        float r1 = rsqrtf(ss1 * (1.f / 128.f) + EPSF) * scl;
        int row0 = bm + wm * 64 + rl;
        if (role == 0) {
#pragma unroll
            for (int nj = 0; nj < 4; ++nj) {
                int d = wn * 32 + nj * 8 + q4 * 2;
                float w0 = nw[d], w1 = nw[d + 1];
                size_t c0 = (size_t)row0 * HIDDIM + bx * 128 + d;
                *(__half2*)(q16 + c0) =
                    __floats2half2_rn(acc[mi][nj][0] * r0 * w0, acc[mi][nj][1] * r0 * w1);
                *(__half2*)(q16 + c0 + (size_t)8 * HIDDIM) =
                    __floats2half2_rn(acc[mi][nj][2] * r1 * w0, acc[mi][nj][3] * r1 * w1);
            }
        } else {
            const int kvh = bx - 16;
            int b0 = row0 >> 11, l0v = row0 & 2047;
            size_t base0 = ((size_t)(b0 * NKVH + kvh) * CLEN + l0v) * HD;
            size_t base1 = base0 + 8 * HD;
#pragma unroll
            for (int nj = 0; nj < 4; ++nj) {
                int d = wn * 32 + nj * 8 + q4 * 2;
                float w0 = nw[d], w1 = nw[d + 1];
                *(__half2*)(k16 + base0 + d) =
                    __floats2half2_rn(acc[mi][nj][0] * r0 * w0, acc[mi][nj][1] * r0 * w1);
                *(__half2*)(k16 + base1 + d) =
                    __floats2half2_rn(acc[mi][nj][2] * r1 * w0, acc[mi][nj][3] * r1 * w1);
            }
        }
    }
}

// ---------------- fp16 flash attention: BQ=64, 4 warps, occ 2 --------------
#define QPITCH  272
#define QBYTES  (64 * QPITCH)       // 17408
#define KVT     (64 * QPITCH)       // 17408
#define KVSTG   (2 * KVT)           // 34816: K, V
#define ATTN_SMEM (QBYTES + 2 * KVSTG)   // 87040

__global__ __launch_bounds__(128, 2) void attn_f16_kernel(
    const __half* __restrict__ q16, const __half* __restrict__ k16,
    const __half* __restrict__ v16, __half* __restrict__ o16)
{
    extern __shared__ char smc[];
    const uint32_t sb = smem_u32(smc);

    const int tid  = threadIdx.x;
    const int lane = tid & 31;
    const int wid  = tid >> 5;
    const int h    = blockIdx.y;
    const int b    = blockIdx.z;
    const int kvh  = h >> 2;
    const int s0   = blockIdx.x * 64;

    const __half* qg = q16 + ((size_t)(b * SEQ + s0) * NH + h) * HD;
    const size_t kvbase = (size_t)(b * NKVH + kvh) * CLEN * HD;

    {
        int chunk = tid & 15, r0 = tid >> 4;
#pragma unroll
        for (int it = 0; it < 8; ++it) {
            int row = r0 + it * 8;
            cpa16(sb + row * QPITCH + chunk * 16, qg + (size_t)row * HIDDIM + chunk * 8);
        }
        CP_COMMIT();
    }

    auto loadKV = [&](int blk, int stage) {
        uint32_t st = sb + QBYTES + stage * KVSTG;
        const __half* pk = k16 + kvbase + (size_t)blk * 64 * HD;
        const __half* pv = v16 + kvbase + (size_t)blk * 64 * HD;
        int chunk = tid & 15, r0 = tid >> 4;
#pragma unroll
        for (int it = 0; it < 8; ++it) {
            int row = r0 + it * 8;
            uint32_t d = st + row * QPITCH + chunk * 16;
            size_t g = (size_t)row * HD + chunk * 8;
            cpa16(d,       pk + g);
            cpa16(d + KVT, pv + g);
        }
        CP_COMMIT();
    };
    loadKV(0, 0);

    float m0 = -1e30f, m1 = -1e30f, l0 = 0.f, l1 = 0.f;
    float ofr[16][4];
#pragma unroll
    for (int f = 0; f < 16; ++f)
#pragma unroll
        for (int r = 0; r < 4; ++r) ofr[f][r] = 0.f;

    const uint32_t laneOff = (lane & 15) * QPITCH + (lane >> 4) * 16;
    const uint32_t qBase = sb + (wid * 16) * QPITCH + laneOff;

    float scA[8][4], scB[8][4];
    uint32_t qreg[8][4];

#define QK_BLOCK(SC, STG) do {                                                   \
    uint32_t kB_ = sb + QBYTES + (STG) * KVSTG + laneOff;                        \
    _Pragma("unroll")                                                            \
    for (int j = 0; j < 8; ++j) {                                                \
        SC[j][0] = 0.f; SC[j][1] = 0.f; SC[j][2] = 0.f; SC[j][3] = 0.f;          \
    }                                                                            \
    _Pragma("unroll")                                                            \
    for (int kc = 0; kc < 8; ++kc) {                                             \
        _Pragma("unroll")                                                        \
        for (int kg = 0; kg < 4; ++kg) {                                         \
            uint32_t kb[4];                                                      \
            ldsm4(kb[0], kb[1], kb[2], kb[3], kB_ + kg * 16 * QPITCH + kc * 32); \
            mma16816(SC[kg * 2],     qreg[kc], kb[0], kb[2]);                    \
            mma16816(SC[kg * 2 + 1], qreg[kc], kb[1], kb[3]);                    \
        }                                                                        \
    }                                                                            \
} while (0)

#define SOFTPV(SC, BLK) do {                                                     \
    float mx0 = -1e30f, mx1 = -1e30f;                                            \
    _Pragma("unroll")                                                            \
    for (int j = 0; j < 8; ++j) {                                                \
        mx0 = fmaxf(mx0, fmaxf(SC[j][0], SC[j][1]));                             \
        mx1 = fmaxf(mx1, fmaxf(SC[j][2], SC[j][3]));                             \
    }                                                                            \
    mx0 = fmaxf(mx0, __shfl_xor_sync(0xffffffffu, mx0, 1));                      \
    mx0 = fmaxf(mx0, __shfl_xor_sync(0xffffffffu, mx0, 2));                      \
    mx1 = fmaxf(mx1, __shfl_xor_sync(0xffffffffu, mx1, 1));                      \
    mx1 = fmaxf(mx1, __shfl_xor_sync(0xffffffffu, mx1, 2));                      \
    bool up_ = __any_sync(0xffffffffu, (mx0 > m0) || (mx1 > m1));                \
    if (up_) {                                                                   \
        float c0_ = ex2f(m0 - fmaxf(m0, mx0)), c1_ = ex2f(m1 - fmaxf(m1, mx1));  \
        m0 = fmaxf(m0, mx0); m1 = fmaxf(m1, mx1);                                \
        l0 *= c0_; l1 *= c1_;                                                    \
        _Pragma("unroll")                                                        \
        for (int f = 0; f < 16; ++f) {                                           \
            ofr[f][0] *= c0_; ofr[f][1] *= c0_;                                  \
            ofr[f][2] *= c1_; ofr[f][3] *= c1_;                                  \
        }                                                                        \
    }                                                                            \
    float rs0 = 0.f, rs1 = 0.f;                                                  \
    _Pragma("unroll")                                                            \
    for (int j = 0; j < 8; ++j) {                                                \
        SC[j][0] = ex2f(SC[j][0] - m0); rs0 += SC[j][0];                         \
        SC[j][1] = ex2f(SC[j][1] - m0); rs0 += SC[j][1];                         \
        SC[j][2] = ex2f(SC[j][2] - m1); rs1 += SC[j][2];                         \
        SC[j][3] = ex2f(SC[j][3] - m1); rs1 += SC[j][3];                         \
    }                                                                            \
    rs0 += __shfl_xor_sync(0xffffffffu, rs0, 1);                                 \
    rs0 += __shfl_xor_sync(0xffffffffu, rs0, 2);                                 \
    rs1 += __shfl_xor_sync(0xffffffffu, rs1, 1);                                 \
    rs1 += __shfl_xor_sync(0xffffffffu, rs1, 2);                                 \
    l0 += rs0;                                                                   \
    l1 += rs1;                                                                   \
    uint32_t pa[4][4];                                                           \
    _Pragma("unroll")                                                            \
    for (int kc = 0; kc < 4; ++kc) {                                             \
        _Pragma("unroll")                                                        \
        for (int hf = 0; hf < 2; ++hf) {                                         \
            pa[kc][hf * 2]     = packh2(SC[2 * kc + hf][0], SC[2 * kc + hf][1]); \
            pa[kc][hf * 2 + 1] = packh2(SC[2 * kc + hf][2], SC[2 * kc + hf][3]); \
        }                                                                        \
    }                                                                            \
    uint32_t vB_ = sb + QBYTES + ((BLK) & 1) * KVSTG + KVT + laneOff;            \
    _Pragma("unroll")                                                            \
    for (int dg = 0; dg < 8; ++dg) {                                             \
        _Pragma("unroll")                                                        \
        for (int kc = 0; kc < 4; ++kc) {                                         \
            uint32_t vb[4];                                                      \
            ldsm4t(vb[0], vb[1], vb[2], vb[3], vB_ + kc * 16 * QPITCH + dg * 32);\
            mma16816(ofr[dg * 2],     pa[kc], vb[0], vb[1]);                     \
            mma16816(ofr[dg * 2 + 1], pa[kc], vb[2], vb[3]);                     \
        }                                                                        \
    }                                                                            \
} while (0)

    asm volatile("cp.async.wait_group 0;" ::: "memory");
    __syncthreads();
#pragma unroll
    for (int kc = 0; kc < 8; ++kc)
        ldsm4(qreg[kc][0], qreg[kc][1], qreg[kc][2], qreg[kc][3], qBase + kc * 32);
    QK_BLOCK(scA, 0);

#pragma unroll 1
    for (int blk = 0; blk < 32; blk += 2) {
        if (blk + 1 < 32) loadKV(blk + 1, (blk + 1) & 1);
        SOFTPV(scA, blk);
        if (blk + 1 < 32) {
            asm volatile("cp.async.wait_group 0;" ::: "memory");
            __syncthreads();
            QK_BLOCK(scB, (blk + 1) & 1);
        }
        if (blk + 2 < 32) loadKV(blk + 2, (blk + 2) & 1);
        if (blk + 1 < 32) SOFTPV(scB, blk + 1);
        if (blk + 2 < 32) {
            asm volatile("cp.async.wait_group 0;" ::: "memory");
            __syncthreads();
            QK_BLOCK(scA, (blk + 2) & 1);
        }
    }

    float inv0 = 1.f / l0, inv1 = 1.f / l1;
    int rowA = b * SEQ + s0 + wid * 16 + (lane >> 2);
    int colB = h * HD + (lane & 3) * 2;
#pragma unroll
    for (int f = 0; f < 16; ++f) {
        int col = colB + f * 8;
        *(__half2*)(o16 + (size_t)rowA * HIDDIM + col) =
            __floats2half2_rn(ofr[f][0] * inv0, ofr[f][1] * inv0);
        *(__half2*)(o16 + (size_t)(rowA + 8) * HIDDIM + col) =
            __floats2half2_rn(ofr[f][2] * inv1, ofr[f][3] * inv1);
    }
}

// ---------------- launch ----------------------------------------------------
extern "C" void kernel_launch(void* const* d_in, const int* in_sizes, int n_in,
                              void* d_out, int out_size)
{
    (void)in_sizes; (void)n_in; (void)out_size;
    const float* x   = (const float*)d_in[0];
    const float* c   = (const float*)d_in[1];
    const float* wq  = (const float*)d_in[2];
    const float* wkv = (const float*)d_in[3];
    const float* wo  = (const float*)d_in[4];
    const float* nqw = (const float*)d_in[5];
    const float* nkw = (const float*)d_in[6];
    float* out = (float*)d_out;

    __half *x16, *c16, *q16, *k16, *v16, *wqT, *wkvT, *woT;
    cudaGetSymbolAddress((void**)&x16,  g_x16);
    cudaGetSymbolAddress((void**)&c16,  g_c16);
    cudaGetSymbolAddress((void**)&q16,  g_q16);
    cudaGetSymbolAddress((void**)&k16,  g_k16);
    cudaGetSymbolAddress((void**)&v16,  g_v16);
    cudaGetSymbolAddress((void**)&wqT,  g_wqT);
    cudaGetSymbolAddress((void**)&wkvT, g_wkvT);
    cudaGetSymbolAddress((void**)&woT,  g_woT);

    const int M = BATCH * SEQ;            // 4096
    const int K = HIDDIM;                 // 2048
    const int gemm128_smem = 3 * STB128;  // 61440
    cudaFuncSetAttribute(gemm_qkv128_kernel,
                         cudaFuncAttributeMaxDynamicSharedMemorySize, gemm128_smem);
    cudaFuncSetAttribute(gemm_o_kernel,
                         cudaFuncAttributeMaxDynamicSharedMemorySize, gemm128_smem);
    cudaFuncSetAttribute(attn_f16_kernel,
                         cudaFuncAttributeMaxDynamicSharedMemorySize, ATTN_SMEM);

    // 0) all conversions in one launch (wkv de-interleaved)
    prep_kernel<<<26624, 256>>>((const float4*)x, (const float4*)c,
                                wq, wkv, wo, x16, c16, wqT, wkvT, woT);

    // 1) Q + K + V projections in one launch (24 x 32 tiles of 128x128, occ 2)
    gemm_qkv128_kernel<<<dim3(24, M / 128), 256, gemm128_smem>>>(
        x16, wqT, nqw, q16, c16, wkvT, nkw, k16, v16);

    // 2) attention: BQ=64, 4 warps, occ 2 per SM
    attn_f16_kernel<<<dim3(SEQ / 64, NH, BATCH), 128, ATTN_SMEM>>>(
        q16, k16, v16, x16);

    // 3) output projection (128x128, occ 2) -> fp32 out
    gemm_o_kernel<<<dim3(HIDDIM / 128, M / 128), 256, gemm128_smem>>>(
        x16, woT, out, M, HIDDIM, K);
}